// round 2
// baseline (speedup 1.0000x reference)
#include <cuda_runtime.h>
#include <cuda_bf16.h>
#include <cstdint>
#include <cstdio>

// ---------------- problem constants (fixed by reference setup) ----------------
#define Hc   256
#define H4c  64          // float4 per row
#define Bc   256         // num graphs
#define Mc   128         // max nodes per graph
#define NHc  8           // heads
#define DHc  32          // head dim
#define NMAX 32768       // total nodes (B*M)

// ---------------- device scratch (static: no allocations allowed) -------------
__device__ float g_agg   [NMAX * Hc];
__device__ float g_z1    [NMAX * Hc];
__device__ float g_pre   [NMAX * Hc];
__device__ float g_hlocal[NMAX * Hc];
__device__ float g_hd    [Bc * Mc * Hc];
__device__ float g_qkv   [Bc * Mc * 3 * Hc];
__device__ float g_adense[Bc * Mc * Hc];
__device__ float g_ao    [Bc * Mc * Hc];
__device__ float g_hh    [NMAX * Hc];
__device__ float g_f1    [NMAX * 2 * Hc];
__device__ float g_stats [2 * Hc];      // [0:H) sum, [H:2H) sumsq
__device__ int   g_cum   [Bc + 1];
__device__ int   g_idx   [NMAX];
__device__ int   g_mask  [Bc * Mc];

// ---------------- small utility kernels ---------------------------------------
__global__ void zero_f4(float4* p, int n4) {
    int i = blockIdx.x * 256 + threadIdx.x;
    if (i < n4) p[i] = make_float4(0.f, 0.f, 0.f, 0.f);
}

// edge scatter-add: agg[dst] += h[src], vectorized red.global.add.v4.f32
__global__ void scatter_edges(const float* __restrict__ h,
                              const int* __restrict__ src,
                              const int* __restrict__ dst, int E) {
    long gid = (long)blockIdx.x * 256 + threadIdx.x;
    if (gid >= (long)E * H4c) return;
    int e = (int)(gid >> 6);
    int c = (int)(gid & 63);
    int s = __ldg(&src[e]);
    int d = __ldg(&dst[e]);
    float4 v = ((const float4*)h)[(size_t)s * H4c + c];
    float4* p = ((float4*)g_agg) + (size_t)d * H4c + c;
    asm volatile("red.global.add.v4.f32 [%0], {%1,%2,%3,%4};"
                 :: "l"(p), "f"(v.x), "f"(v.y), "f"(v.z), "f"(v.w) : "memory");
}

// ---------------- SGEMM: C = act((A [+A2]) @ W^T + bias [+res]) ---------------
// A: [Mr, K] row-major, W: [Nc, K] row-major, C: [Mr, Nc].
// BM=128, BN=64, BK=16; 256 threads; each thread 8x4 outputs.
template<bool RELU>
__global__ __launch_bounds__(256)
void sgemm_k(const float* __restrict__ A, const float* __restrict__ A2,
             const float* __restrict__ W, const float* __restrict__ bias,
             const float* __restrict__ res, float* __restrict__ C,
             int Nc, int K) {
    __shared__ float As[16][132];
    __shared__ float Bs[16][68];
    const int tid = threadIdx.x;
    const int ty = tid >> 4, tx = tid & 15;
    const int row0 = blockIdx.y * 128;
    const int col0 = blockIdx.x * 64;
    float acc[8][4];
#pragma unroll
    for (int i = 0; i < 8; i++)
#pragma unroll
        for (int j = 0; j < 4; j++) acc[i][j] = 0.f;

    for (int k0 = 0; k0 < K; k0 += 16) {
#pragma unroll
        for (int i = 0; i < 2; i++) {
            int id = tid + i * 256;
            int r = id >> 2, c4 = (id & 3) * 4;
            float4 v = *(const float4*)(A + (size_t)(row0 + r) * K + k0 + c4);
            if (A2) {
                float4 w = *(const float4*)(A2 + (size_t)(row0 + r) * K + k0 + c4);
                v.x += w.x; v.y += w.y; v.z += w.z; v.w += w.w;
            }
            As[c4 + 0][r] = v.x; As[c4 + 1][r] = v.y;
            As[c4 + 2][r] = v.z; As[c4 + 3][r] = v.w;
        }
        {
            int r = tid >> 2, c4 = (tid & 3) * 4;
            float4 v = *(const float4*)(W + (size_t)(col0 + r) * K + k0 + c4);
            Bs[c4 + 0][r] = v.x; Bs[c4 + 1][r] = v.y;
            Bs[c4 + 2][r] = v.z; Bs[c4 + 3][r] = v.w;
        }
        __syncthreads();
#pragma unroll
        for (int kk = 0; kk < 16; kk++) {
            float a[8], b[4];
            *(float4*)&a[0] = *(const float4*)&As[kk][ty * 8];
            *(float4*)&a[4] = *(const float4*)&As[kk][ty * 8 + 4];
            *(float4*)&b[0] = *(const float4*)&Bs[kk][tx * 4];
#pragma unroll
            for (int i = 0; i < 8; i++)
#pragma unroll
                for (int j = 0; j < 4; j++) acc[i][j] += a[i] * b[j];
        }
        __syncthreads();
    }

    float4 bi = *(const float4*)(bias + col0 + tx * 4);
#pragma unroll
    for (int i = 0; i < 8; i++) {
        int row = row0 + ty * 8 + i;
        float4 o;
        o.x = acc[i][0] + bi.x; o.y = acc[i][1] + bi.y;
        o.z = acc[i][2] + bi.z; o.w = acc[i][3] + bi.w;
        if (res) {
            float4 r4 = *(const float4*)(res + (size_t)row * Nc + col0 + tx * 4);
            o.x += r4.x; o.y += r4.y; o.z += r4.z; o.w += r4.w;
        }
        if (RELU) {
            o.x = fmaxf(o.x, 0.f); o.y = fmaxf(o.y, 0.f);
            o.z = fmaxf(o.z, 0.f); o.w = fmaxf(o.w, 0.f);
        }
        *(float4*)(C + (size_t)row * Nc + col0 + tx * 4) = o;
    }
}

// ---------------- BatchNorm stats + apply --------------------------------------
__global__ void bn_stats(const float* __restrict__ X) {
    int c = threadIdx.x;               // 256 threads = channels
    int r0 = blockIdx.x * 128;
    float s = 0.f, q = 0.f;
    for (int i = 0; i < 128; i++) {
        float x = X[(size_t)(r0 + i) * Hc + c];
        s += x; q += x * x;
    }
    atomicAdd(&g_stats[c], s);
    atomicAdd(&g_stats[Hc + c], q);
}

// out = gamma*(X-mean)*rsqrt(var+eps)+beta  [+ addp]
__global__ void bn_apply(const float* __restrict__ X,
                         const float* __restrict__ gamma,
                         const float* __restrict__ beta,
                         const float* __restrict__ addp,
                         float* __restrict__ out, float invN, int n4total) {
    int gid = blockIdx.x * 256 + threadIdx.x;
    if (gid >= n4total) return;
    int c4 = gid & 63;
    float4 x = ((const float4*)X)[gid];
    float4 s = ((const float4*)g_stats)[c4];
    float4 q = ((const float4*)g_stats)[H4c + c4];
    float4 g = ((const float4*)gamma)[c4];
    float4 b = ((const float4*)beta)[c4];
    float4 o;
    {
        float m = s.x * invN, v = q.x * invN - m * m;
        o.x = g.x * (x.x - m) * rsqrtf(v + 1e-5f) + b.x;
    }
    {
        float m = s.y * invN, v = q.y * invN - m * m;
        o.y = g.y * (x.y - m) * rsqrtf(v + 1e-5f) + b.y;
    }
    {
        float m = s.z * invN, v = q.z * invN - m * m;
        o.z = g.z * (x.z - m) * rsqrtf(v + 1e-5f) + b.z;
    }
    {
        float m = s.w * invN, v = q.w * invN - m * m;
        o.w = g.w * (x.w - m) * rsqrtf(v + 1e-5f) + b.w;
    }
    if (addp) {
        float4 a = ((const float4*)addp)[gid];
        o.x += a.x; o.y += a.y; o.z += a.z; o.w += a.w;
    }
    ((float4*)out)[gid] = o;
}

// ---------------- dense-batch index machinery ----------------------------------
__global__ void scan_k(const int* __restrict__ bnn, int B) {
    __shared__ int sm[256];
    int t = threadIdx.x;
    sm[t] = (t < B) ? bnn[t] : 0;
    __syncthreads();
    for (int off = 1; off < 256; off <<= 1) {
        int v = sm[t] + ((t >= off) ? sm[t - off] : 0);
        __syncthreads();
        sm[t] = v;
        __syncthreads();
    }
    if (t == 0) g_cum[0] = 0;
    if (t < B) g_cum[t + 1] = sm[t];
}

__global__ void idx_k(int nN, int B) {
    int n = blockIdx.x * 256 + threadIdx.x;
    if (n >= nN) return;
    int lo = 0, hi = B - 1;
    while (lo < hi) {
        int mid = (lo + hi) >> 1;
        if (g_cum[mid + 1] > n) hi = mid; else lo = mid + 1;
    }
    g_idx[n] = n - g_cum[lo] + lo * Mc;
}

// scatter the ORIGINAL h into the dense batch (reference: .at[idx].set(h))
__global__ void scatter_dense(const float* __restrict__ h, int nN) {
    long gid = (long)blockIdx.x * 256 + threadIdx.x;
    if (gid >= (long)nN * H4c) return;
    int n = (int)(gid >> 6), c = (int)(gid & 63);
    int id = g_idx[n];
    ((float4*)g_hd)[(size_t)id * H4c + c] = ((const float4*)h)[gid];
}

__global__ void set_mask(int nN) {
    int n = blockIdx.x * 256 + threadIdx.x;
    if (n < nN) g_mask[g_idx[n]] = 1;
}

__global__ void gather_res(const float* __restrict__ h, int nN) {
    long gid = (long)blockIdx.x * 256 + threadIdx.x;
    if (gid >= (long)nN * H4c) return;
    int n = (int)(gid >> 6), c = (int)(gid & 63);
    int id = g_idx[n];
    float4 a = ((const float4*)h)[gid];
    float4 b = ((const float4*)g_ao)[(size_t)id * H4c + c];
    a.x += b.x; a.y += b.y; a.z += b.z; a.w += b.w;
    ((float4*)g_pre)[gid] = a;
}

// ---------------- attention -----------------------------------------------------
// FMA-pipe exp (avoids MUFU ceiling): deg-7 Taylor of 2^f, rel err ~1.3e-6.
__device__ __forceinline__ float fast_exp(float x) {
    x = fmaxf(x, -87.0f);
    float t = x * 1.44269504088896341f;
    float fn = floorf(t);
    float f = t - fn;
    float p = 1.52527338418689e-5f;
    p = p * f + 1.54035303489144e-4f;
    p = p * f + 1.33335581464294e-3f;
    p = p * f + 9.61812910762848e-3f;
    p = p * f + 5.55041086648216e-2f;
    p = p * f + 2.40226506959101e-1f;
    p = p * f + 6.93147180559945e-1f;
    p = p * f + 1.0f;
    int n = (int)fn;
    return p * __int_as_float((n + 127) << 23);
}

// one block per (graph b, head): 128 threads, thread = query row.
__global__ __launch_bounds__(128)
void attn_k() {
    int b = blockIdx.x / NHc;
    int head = blockIdx.x % NHc;
    __shared__ float Ks[Mc * DHc];
    __shared__ float Vs[Mc * DHc];
    __shared__ int msk[Mc];
    int tid = threadIdx.x;

    const float* qkv = g_qkv;
    // K/V tiles coalesced: 1024 float4, 8 per thread
#pragma unroll
    for (int i = 0; i < 8; i++) {
        int id = tid + i * 128;
        int kp = id >> 3, d4 = id & 7;
        size_t row = (size_t)(b * Mc + kp) * (3 * Hc);
        ((float4*)Ks)[kp * 8 + d4] =
            *(const float4*)(qkv + row + Hc + head * DHc + d4 * 4);
        ((float4*)Vs)[kp * 8 + d4] =
            *(const float4*)(qkv + row + 2 * Hc + head * DHc + d4 * 4);
    }
    msk[tid] = g_mask[b * Mc + tid];
    __syncthreads();

    float qr[DHc];
    {
        const float* qp = qkv + (size_t)(b * Mc + tid) * (3 * Hc) + head * DHc;
#pragma unroll
        for (int d4 = 0; d4 < 8; d4++)
            *(float4*)&qr[d4 * 4] = *(const float4*)(qp + d4 * 4);
    }

    float mx = -3.0e38f, l = 0.f;
    float acc[DHc];
#pragma unroll
    for (int d = 0; d < DHc; d++) acc[d] = 0.f;

    const float scale = 0.17677669529663687f;  // 1/sqrt(32)
    for (int kp = 0; kp < Mc; kp++) {
        const float* kr = &Ks[kp * DHc];
        float s = 0.f;
#pragma unroll
        for (int d = 0; d < DHc; d++) s += qr[d] * kr[d];
        s *= scale;
        if (!msk[kp]) s = -1e9f;
        float mn = fmaxf(mx, s);
        float corr = fast_exp(mx - mn);
        float p = fast_exp(s - mn);
        l = l * corr + p;
        const float* vr = &Vs[kp * DHc];
#pragma unroll
        for (int d = 0; d < DHc; d++) acc[d] = acc[d] * corr + p * vr[d];
        mx = mn;
    }
    float inv = 1.f / l;
    float* op = g_adense + (size_t)(b * Mc + tid) * Hc + head * DHc;
#pragma unroll
    for (int d4 = 0; d4 < 8; d4++) {
        float4 o;
        o.x = acc[d4 * 4 + 0] * inv; o.y = acc[d4 * 4 + 1] * inv;
        o.z = acc[d4 * 4 + 2] * inv; o.w = acc[d4 * 4 + 3] * inv;
        *(float4*)(op + d4 * 4) = o;
    }
}

// ---------------- host orchestration -------------------------------------------
static inline int cdiv(long a, int b) { return (int)((a + b - 1) / b); }

extern "C" void kernel_launch(void* const* d_in, const int* in_sizes, int n_in,
                              void* d_out, int out_size) {
    const float* h         = (const float*)d_in[0];
    const float* gin_w1    = (const float*)d_in[1];
    const float* gin_b1    = (const float*)d_in[2];
    const float* gin_w2    = (const float*)d_in[3];
    const float* gin_b2    = (const float*)d_in[4];
    const float* in_proj_w = (const float*)d_in[5];
    const float* in_proj_b = (const float*)d_in[6];
    const float* out_proj_w= (const float*)d_in[7];
    const float* out_proj_b= (const float*)d_in[8];
    const float* bnl_g     = (const float*)d_in[9];
    const float* bnl_b     = (const float*)d_in[10];
    const float* bna_g     = (const float*)d_in[11];
    const float* bna_b     = (const float*)d_in[12];
    const float* bno_g     = (const float*)d_in[13];
    const float* bno_b     = (const float*)d_in[14];
    const float* ffn1_w    = (const float*)d_in[15];
    const float* ffn1_b    = (const float*)d_in[16];
    const float* ffn2_w    = (const float*)d_in[17];
    const float* ffn2_b    = (const float*)d_in[18];
    const int*   e_src     = (const int*)d_in[19];
    const int*   e_dst     = (const int*)d_in[20];
    const int*   bnn       = (const int*)d_in[21];

    const int nN = in_sizes[0] / Hc;      // 32768
    const int nE = in_sizes[19];          // 524288
    const int nB = in_sizes[21];          // 256
    const int n4 = nN * H4c;              // float4 count of an [N,H] tensor
    const float invN = 1.0f / (float)nN;

    float *p_agg, *p_z1, *p_pre, *p_hlocal, *p_hd, *p_qkv, *p_adense, *p_ao,
          *p_hh, *p_f1, *p_stats, *p_mask;
    cudaGetSymbolAddress((void**)&p_agg,    g_agg);
    cudaGetSymbolAddress((void**)&p_z1,     g_z1);
    cudaGetSymbolAddress((void**)&p_pre,    g_pre);
    cudaGetSymbolAddress((void**)&p_hlocal, g_hlocal);
    cudaGetSymbolAddress((void**)&p_hd,     g_hd);
    cudaGetSymbolAddress((void**)&p_qkv,    g_qkv);
    cudaGetSymbolAddress((void**)&p_adense, g_adense);
    cudaGetSymbolAddress((void**)&p_ao,     g_ao);
    cudaGetSymbolAddress((void**)&p_hh,     g_hh);
    cudaGetSymbolAddress((void**)&p_f1,     g_f1);
    cudaGetSymbolAddress((void**)&p_stats,  g_stats);
    cudaGetSymbolAddress((void**)&p_mask,   g_mask);

    auto gemm = [&](bool relu, const float* A, const float* A2, const float* W,
                    const float* bias, const float* res, float* C, int Nc, int K) {
        dim3 grid(Nc / 64, nN / 128);
        if (relu) sgemm_k<true ><<<grid, 256>>>(A, A2, W, bias, res, C, Nc, K);
        else      sgemm_k<false><<<grid, 256>>>(A, A2, W, bias, res, C, Nc, K);
    };
    auto zero = [&](float* p, long nfloats) {
        int nn4 = (int)(nfloats / 4);
        zero_f4<<<cdiv(nn4, 256), 256>>>((float4*)p, nn4);
    };

    // ---- GIN local branch ----
    zero(p_agg, (long)nN * Hc);
    scatter_edges<<<cdiv((long)nE * H4c, 256), 256>>>(h, e_src, e_dst, nE);
    gemm(true,  h,    p_agg, gin_w1, gin_b1, nullptr, p_z1,  Hc, Hc);
    gemm(false, p_z1, nullptr, gin_w2, gin_b2, h,     p_pre, Hc, Hc);
    zero(p_stats, 2 * Hc);
    bn_stats<<<nN / 128, Hc>>>(p_pre);
    bn_apply<<<cdiv(n4, 256), 256>>>(p_pre, bnl_g, bnl_b, nullptr, p_hlocal, invN, n4);

    // ---- dense batch scatter (of the ORIGINAL h) ----
    scan_k<<<1, 256>>>(bnn, nB);
    idx_k<<<cdiv(nN, 256), 256>>>(nN, nB);
    zero(p_hd, (long)Bc * Mc * Hc);
    zero(p_mask, Bc * Mc);            // int array zeroed as floats (same bits)
    scatter_dense<<<cdiv((long)nN * H4c, 256), 256>>>(h, nN);
    set_mask<<<cdiv(nN, 256), 256>>>(nN);

    // ---- attention ----
    gemm(false, p_hd, nullptr, in_proj_w, in_proj_b, nullptr, p_qkv, 3 * Hc, Hc);
    attn_k<<<Bc * NHc, Mc>>>();
    gemm(false, p_adense, nullptr, out_proj_w, out_proj_b, nullptr, p_ao, Hc, Hc);
    gather_res<<<cdiv((long)nN * H4c, 256), 256>>>(h, nN);
    zero(p_stats, 2 * Hc);
    bn_stats<<<nN / 128, Hc>>>(p_pre);
    bn_apply<<<cdiv(n4, 256), 256>>>(p_pre, bna_g, bna_b, p_hlocal, p_hh, invN, n4);

    // ---- FFN + out norm ----
    gemm(true,  p_hh, nullptr, ffn1_w, ffn1_b, nullptr, p_f1,  2 * Hc, Hc);
    gemm(false, p_f1, nullptr, ffn2_w, ffn2_b, p_hh,    p_pre, Hc, 2 * Hc);
    zero(p_stats, 2 * Hc);
    bn_stats<<<nN / 128, Hc>>>(p_pre);
    bn_apply<<<cdiv(n4, 256), 256>>>(p_pre, bno_g, bno_b, nullptr, (float*)d_out, invN, n4);
}

// round 4
// speedup vs baseline: 1.5340x; 1.5340x over previous
#include <cuda_runtime.h>
#include <cuda_bf16.h>
#include <cstdint>
#include <cstdio>

// ---------------- problem constants ----------------
#define Hc   256
#define H4c  64
#define Bc   256
#define Mc   128
#define NHc  8
#define DHc  32
#define NMAX 32768

// ---------------- device scratch -------------------
__device__ float g_agg   [NMAX * Hc];
__device__ float g_z1    [NMAX * Hc];
__device__ float g_pre   [NMAX * Hc];
__device__ float g_hlocal[NMAX * Hc];
__device__ float g_hd    [Bc * Mc * Hc];
__device__ float g_qkv   [Bc * Mc * 3 * Hc];
__device__ float g_adense[Bc * Mc * Hc];
__device__ float g_ao    [Bc * Mc * Hc];
__device__ float g_hh    [NMAX * Hc];
__device__ float g_f1    [NMAX * 2 * Hc];
__device__ float g_stats [2 * Hc];
__device__ int   g_cum   [Bc + 1];
__device__ int   g_idx   [NMAX];
__device__ int   g_mask  [Bc * Mc];
// pre-split weights (bf16 hi/lo)
#define WTOT 655360
__device__ __align__(16) __nv_bfloat16 g_whi[WTOT];
__device__ __align__(16) __nv_bfloat16 g_wlo[WTOT];

// ---------------- PTX helpers ----------------------
__device__ __forceinline__ uint32_t smem_u32(const void* p) {
    uint32_t a;
    asm("{ .reg .u64 t; cvta.to.shared.u64 t, %1; cvt.u32.u64 %0, t; }"
        : "=r"(a) : "l"(p));
    return a;
}
#define LDSM_X4(r0, r1, r2, r3, addr)                                    \
    asm volatile("ldmatrix.sync.aligned.m8n8.x4.shared.b16 {%0,%1,%2,%3}, [%4];" \
                 : "=r"(r0), "=r"(r1), "=r"(r2), "=r"(r3) : "r"(addr))
#define MMA16816(d, a, b0, b1)                                           \
    asm volatile("mma.sync.aligned.m16n8k16.row.col.f32.bf16.bf16.f32 "  \
                 "{%0,%1,%2,%3}, {%4,%5,%6,%7}, {%8,%9}, {%0,%1,%2,%3};" \
                 : "+f"((d)[0]), "+f"((d)[1]), "+f"((d)[2]), "+f"((d)[3]) \
                 : "r"((a)[0]), "r"((a)[1]), "r"((a)[2]), "r"((a)[3]),   \
                   "r"(b0), "r"(b1))
#define CP_ASYNC16(dst, src)                                             \
    asm volatile("cp.async.ca.shared.global [%0], [%1], 16;" :: "r"(dst), "l"(src))
#define CP_COMMIT() asm volatile("cp.async.commit_group;")
#define CP_WAIT0()  asm volatile("cp.async.wait_group 0;" ::: "memory")

__device__ __forceinline__ uint32_t pack_bf2(__nv_bfloat16 a, __nv_bfloat16 b) {
    __nv_bfloat162 p{a, b};
    return *(uint32_t*)&p;
}

// ---------------- mma.sync bf16 hi/lo GEMM ---------
// C[128,128] tile = act((A[+A2]) @ W^T + bias [+res]); A fp32, W pre-split bf16.
// BK=32, row stride 40 bf16 (80B) -> conflict-free ldmatrix.
#define ROWB 80                   // bytes per smem row
#define OFF_AHI 0
#define OFF_ALO 10240
#define OFF_BHI 20480
#define OFF_BLO 30720
#define BUFSZ   40960
#define GEMM_SMEM (2 * BUFSZ)

template<bool RELU>
__global__ __launch_bounds__(256, 2)
void mma_gemm(const float* __restrict__ A, const float* __restrict__ A2,
              const __nv_bfloat16* __restrict__ Whi, const __nv_bfloat16* __restrict__ Wlo,
              const float* __restrict__ bias, const float* __restrict__ res,
              float* __restrict__ C, int Nc, int K) {
    extern __shared__ char smem[];
    const uint32_t sb = smem_u32(smem);
    const int tid = threadIdx.x;
    const int wid = tid >> 5, lane = tid & 31;
    const int wm = (wid >> 1) * 32, wn = (wid & 1) * 64;
    const int row0 = blockIdx.y * 128;
    const int col0 = blockIdx.x * 128;

    const int r = tid >> 1, half = tid & 1;   // staging thread coords

    float acc[2][8][4];
#pragma unroll
    for (int mt = 0; mt < 2; mt++)
#pragma unroll
        for (int nt = 0; nt < 8; nt++)
#pragma unroll
            for (int q = 0; q < 4; q++) acc[mt][nt][q] = 0.f;

    const int nit = K >> 5;
    float4 va[4];

    // ---- prologue: A tile0 -> regs, B tile0 -> cp.async buf0 ----
    {
        const float* ap = A + (size_t)(row0 + r) * K + half * 16;
#pragma unroll
        for (int j = 0; j < 4; j++) va[j] = *(const float4*)(ap + j * 4);
        if (A2) {
            const float* ap2 = A2 + (size_t)(row0 + r) * K + half * 16;
#pragma unroll
            for (int j = 0; j < 4; j++) {
                float4 w = *(const float4*)(ap2 + j * 4);
                va[j].x += w.x; va[j].y += w.y; va[j].z += w.z; va[j].w += w.w;
            }
        }
        const char* gbh = (const char*)(Whi + (size_t)(col0 + r) * K + half * 16);
        const char* gbl = (const char*)(Wlo + (size_t)(col0 + r) * K + half * 16);
        uint32_t d0 = sb + OFF_BHI + r * ROWB + half * 32;
        uint32_t d1 = sb + OFF_BLO + r * ROWB + half * 32;
        CP_ASYNC16(d0, gbh); CP_ASYNC16(d0 + 16, gbh + 16);
        CP_ASYNC16(d1, gbl); CP_ASYNC16(d1 + 16, gbl + 16);
        CP_COMMIT();
    }

    for (int i = 0; i < nit; i++) {
        const uint32_t boff = (uint32_t)(i & 1) * BUFSZ;
        // ---- convert + STS A tile i ----
        {
            uint32_t hv[8], lv[8];
#pragma unroll
            for (int j = 0; j < 4; j++) {
                float4 v = va[j];
                __nv_bfloat16 hx = __float2bfloat16_rn(v.x), hy = __float2bfloat16_rn(v.y);
                __nv_bfloat16 hz = __float2bfloat16_rn(v.z), hw = __float2bfloat16_rn(v.w);
                hv[j * 2 + 0] = pack_bf2(hx, hy);
                hv[j * 2 + 1] = pack_bf2(hz, hw);
                lv[j * 2 + 0] = pack_bf2(__float2bfloat16_rn(v.x - __bfloat162float(hx)),
                                         __float2bfloat16_rn(v.y - __bfloat162float(hy)));
                lv[j * 2 + 1] = pack_bf2(__float2bfloat16_rn(v.z - __bfloat162float(hz)),
                                         __float2bfloat16_rn(v.w - __bfloat162float(hw)));
            }
            char* pa = smem + boff + OFF_AHI + r * ROWB + half * 32;
            *(uint4*)pa = *(uint4*)&hv[0];
            *(uint4*)(pa + 16) = *(uint4*)&hv[4];
            char* pl = smem + boff + OFF_ALO + r * ROWB + half * 32;
            *(uint4*)pl = *(uint4*)&lv[0];
            *(uint4*)(pl + 16) = *(uint4*)&lv[4];
        }
        CP_WAIT0();
        __syncthreads();
        // ---- prefetch tile i+1 ----
        if (i + 1 < nit) {
            const int k0 = (i + 1) * 32;
            const float* ap = A + (size_t)(row0 + r) * K + k0 + half * 16;
#pragma unroll
            for (int j = 0; j < 4; j++) va[j] = *(const float4*)(ap + j * 4);
            if (A2) {
                const float* ap2 = A2 + (size_t)(row0 + r) * K + k0 + half * 16;
#pragma unroll
                for (int j = 0; j < 4; j++) {
                    float4 w = *(const float4*)(ap2 + j * 4);
                    va[j].x += w.x; va[j].y += w.y; va[j].z += w.z; va[j].w += w.w;
                }
            }
            const uint32_t nb = (uint32_t)((i + 1) & 1) * BUFSZ;
            const char* gbh = (const char*)(Whi + (size_t)(col0 + r) * K + k0 + half * 16);
            const char* gbl = (const char*)(Wlo + (size_t)(col0 + r) * K + k0 + half * 16);
            uint32_t d0 = sb + nb + OFF_BHI + r * ROWB + half * 32;
            uint32_t d1 = sb + nb + OFF_BLO + r * ROWB + half * 32;
            CP_ASYNC16(d0, gbh); CP_ASYNC16(d0 + 16, gbh + 16);
            CP_ASYNC16(d1, gbl); CP_ASYNC16(d1 + 16, gbl + 16);
            CP_COMMIT();
        }
        // ---- mma on tile i ----
#pragma unroll
        for (int ks = 0; ks < 2; ks++) {
            uint32_t ah[2][4], al[2][4];
#pragma unroll
            for (int mt = 0; mt < 2; mt++) {
                uint32_t arow = wm + mt * 16 + (lane & 15);
                uint32_t kb = ks * 32 + ((lane >> 4) * 16);
                uint32_t ad = sb + boff + OFF_AHI + arow * ROWB + kb;
                LDSM_X4(ah[mt][0], ah[mt][1], ah[mt][2], ah[mt][3], ad);
                LDSM_X4(al[mt][0], al[mt][1], al[mt][2], al[mt][3],
                        ad + (OFF_ALO - OFF_AHI));
            }
#pragma unroll
            for (int np = 0; np < 4; np++) {
                uint32_t nrow = wn + np * 16 + ((lane >> 4) << 3) + (lane & 7);
                uint32_t kb = ks * 32 + (((lane >> 3) & 1) << 4);
                uint32_t bd = sb + boff + OFF_BHI + nrow * ROWB + kb;
                uint32_t bh[4], bl[4];
                LDSM_X4(bh[0], bh[1], bh[2], bh[3], bd);
                LDSM_X4(bl[0], bl[1], bl[2], bl[3], bd + (OFF_BLO - OFF_BHI));
#pragma unroll
                for (int mt = 0; mt < 2; mt++) {
                    MMA16816(acc[mt][2 * np],     ah[mt], bh[0], bh[1]);
                    MMA16816(acc[mt][2 * np],     al[mt], bh[0], bh[1]);
                    MMA16816(acc[mt][2 * np],     ah[mt], bl[0], bl[1]);
                    MMA16816(acc[mt][2 * np + 1], ah[mt], bh[2], bh[3]);
                    MMA16816(acc[mt][2 * np + 1], al[mt], bh[2], bh[3]);
                    MMA16816(acc[mt][2 * np + 1], ah[mt], bl[2], bl[3]);
                }
            }
        }
    }

    // ---- epilogue ----
#pragma unroll
    for (int mt = 0; mt < 2; mt++) {
        int rA = row0 + wm + mt * 16 + (lane >> 2);
#pragma unroll
        for (int nt = 0; nt < 8; nt++) {
            int c = col0 + wn + nt * 8 + (lane & 3) * 2;
            float2 bi = *(const float2*)(bias + c);
            float o0 = acc[mt][nt][0] + bi.x, o1 = acc[mt][nt][1] + bi.y;
            float o2 = acc[mt][nt][2] + bi.x, o3 = acc[mt][nt][3] + bi.y;
            if (res) {
                float2 r0 = *(const float2*)(res + (size_t)rA * Nc + c);
                float2 r1 = *(const float2*)(res + (size_t)(rA + 8) * Nc + c);
                o0 += r0.x; o1 += r0.y; o2 += r1.x; o3 += r1.y;
            }
            if (RELU) {
                o0 = fmaxf(o0, 0.f); o1 = fmaxf(o1, 0.f);
                o2 = fmaxf(o2, 0.f); o3 = fmaxf(o3, 0.f);
            }
            *(float2*)(C + (size_t)rA * Nc + c) = make_float2(o0, o1);
            *(float2*)(C + (size_t)(rA + 8) * Nc + c) = make_float2(o2, o3);
        }
    }
}

// weight split prepass: fp32 -> bf16 hi/lo
__global__ void wsplit_k(const float* __restrict__ W, __nv_bfloat16* __restrict__ hi,
                         __nv_bfloat16* __restrict__ lo, int n4) {
    int i = blockIdx.x * 256 + threadIdx.x;
    if (i >= n4) return;
    float4 v = ((const float4*)W)[i];
    __nv_bfloat16 hx = __float2bfloat16_rn(v.x), hy = __float2bfloat16_rn(v.y);
    __nv_bfloat16 hz = __float2bfloat16_rn(v.z), hw = __float2bfloat16_rn(v.w);
    uint32_t h0 = pack_bf2(hx, hy), h1 = pack_bf2(hz, hw);
    uint32_t l0 = pack_bf2(__float2bfloat16_rn(v.x - __bfloat162float(hx)),
                           __float2bfloat16_rn(v.y - __bfloat162float(hy)));
    uint32_t l1 = pack_bf2(__float2bfloat16_rn(v.z - __bfloat162float(hz)),
                           __float2bfloat16_rn(v.w - __bfloat162float(hw)));
    ((uint2*)hi)[i] = make_uint2(h0, h1);
    ((uint2*)lo)[i] = make_uint2(l0, l1);
}

// ---------------- utility kernels ------------------
__global__ void zero_f4(float4* p, int n4) {
    int i = blockIdx.x * 256 + threadIdx.x;
    if (i < n4) p[i] = make_float4(0.f, 0.f, 0.f, 0.f);
}

__global__ void scatter_edges(const float* __restrict__ h,
                              const int* __restrict__ src,
                              const int* __restrict__ dst, int E) {
    long gid = (long)blockIdx.x * 256 + threadIdx.x;
    if (gid >= (long)E * H4c) return;
    int e = (int)(gid >> 6);
    int c = (int)(gid & 63);
    int s = __ldg(&src[e]);
    int d = __ldg(&dst[e]);
    float4 v = ((const float4*)h)[(size_t)s * H4c + c];
    float4* p = ((float4*)g_agg) + (size_t)d * H4c + c;
    asm volatile("red.global.add.v4.f32 [%0], {%1,%2,%3,%4};"
                 :: "l"(p), "f"(v.x), "f"(v.y), "f"(v.z), "f"(v.w) : "memory");
}

__global__ void bn_stats(const float* __restrict__ X) {
    int c = threadIdx.x;
    int r0 = blockIdx.x * 128;
    float s = 0.f, q = 0.f;
    for (int i = 0; i < 128; i++) {
        float x = X[(size_t)(r0 + i) * Hc + c];
        s += x; q += x * x;
    }
    atomicAdd(&g_stats[c], s);
    atomicAdd(&g_stats[Hc + c], q);
}

__global__ void bn_apply(const float* __restrict__ X,
                         const float* __restrict__ gamma,
                         const float* __restrict__ beta,
                         const float* __restrict__ addp,
                         float* __restrict__ out, float invN, int n4total) {
    int gid = blockIdx.x * 256 + threadIdx.x;
    if (gid >= n4total) return;
    int c4 = gid & 63;
    float4 x = ((const float4*)X)[gid];
    float4 s = ((const float4*)g_stats)[c4];
    float4 q = ((const float4*)g_stats)[H4c + c4];
    float4 g = ((const float4*)gamma)[c4];
    float4 b = ((const float4*)beta)[c4];
    float4 o;
    { float m = s.x * invN, v = q.x * invN - m * m; o.x = g.x * (x.x - m) * rsqrtf(v + 1e-5f) + b.x; }
    { float m = s.y * invN, v = q.y * invN - m * m; o.y = g.y * (x.y - m) * rsqrtf(v + 1e-5f) + b.y; }
    { float m = s.z * invN, v = q.z * invN - m * m; o.z = g.z * (x.z - m) * rsqrtf(v + 1e-5f) + b.z; }
    { float m = s.w * invN, v = q.w * invN - m * m; o.w = g.w * (x.w - m) * rsqrtf(v + 1e-5f) + b.w; }
    if (addp) {
        float4 a = ((const float4*)addp)[gid];
        o.x += a.x; o.y += a.y; o.z += a.z; o.w += a.w;
    }
    ((float4*)out)[gid] = o;
}

__global__ void scan_k(const int* __restrict__ bnn, int B) {
    __shared__ int sm[256];
    int t = threadIdx.x;
    sm[t] = (t < B) ? bnn[t] : 0;
    __syncthreads();
    for (int off = 1; off < 256; off <<= 1) {
        int v = sm[t] + ((t >= off) ? sm[t - off] : 0);
        __syncthreads();
        sm[t] = v;
        __syncthreads();
    }
    if (t == 0) g_cum[0] = 0;
    if (t < B) g_cum[t + 1] = sm[t];
}

__global__ void idx_k(int nN, int B) {
    int n = blockIdx.x * 256 + threadIdx.x;
    if (n >= nN) return;
    int lo = 0, hi = B - 1;
    while (lo < hi) {
        int mid = (lo + hi) >> 1;
        if (g_cum[mid + 1] > n) hi = mid; else lo = mid + 1;
    }
    g_idx[n] = n - g_cum[lo] + lo * Mc;
}

__global__ void scatter_dense(const float* __restrict__ h, int nN) {
    long gid = (long)blockIdx.x * 256 + threadIdx.x;
    if (gid >= (long)nN * H4c) return;
    int n = (int)(gid >> 6), c = (int)(gid & 63);
    int id = g_idx[n];
    ((float4*)g_hd)[(size_t)id * H4c + c] = ((const float4*)h)[gid];
}

__global__ void set_mask(int nN) {
    int n = blockIdx.x * 256 + threadIdx.x;
    if (n < nN) g_mask[g_idx[n]] = 1;
}

__global__ void gather_res(const float* __restrict__ h, int nN) {
    long gid = (long)blockIdx.x * 256 + threadIdx.x;
    if (gid >= (long)nN * H4c) return;
    int n = (int)(gid >> 6), c = (int)(gid & 63);
    int id = g_idx[n];
    float4 a = ((const float4*)h)[gid];
    float4 b = ((const float4*)g_ao)[(size_t)id * H4c + c];
    a.x += b.x; a.y += b.y; a.z += b.z; a.w += b.w;
    ((float4*)g_pre)[gid] = a;
}

// ---------------- attention ------------------------
__device__ __forceinline__ float fast_exp(float x) {
    x = fmaxf(x, -87.0f);
    float t = x * 1.44269504088896341f;
    float fn = floorf(t);
    float f = t - fn;
    float p = 1.52527338418689e-5f;
    p = p * f + 1.54035303489144e-4f;
    p = p * f + 1.33335581464294e-3f;
    p = p * f + 9.61812910762848e-3f;
    p = p * f + 5.55041086648216e-2f;
    p = p * f + 2.40226506959101e-1f;
    p = p * f + 6.93147180559945e-1f;
    p = p * f + 1.0f;
    int n = (int)fn;
    return p * __int_as_float((n + 127) << 23);
}

__global__ __launch_bounds__(128)
void attn_k() {
    int b = blockIdx.x / NHc;
    int head = blockIdx.x % NHc;
    __shared__ float Ks[Mc * DHc];
    __shared__ float Vs[Mc * DHc];
    __shared__ int msk[Mc];
    int tid = threadIdx.x;

    const float* qkv = g_qkv;
#pragma unroll
    for (int i = 0; i < 8; i++) {
        int id = tid + i * 128;
        int kp = id >> 3, d4 = id & 7;
        size_t row = (size_t)(b * Mc + kp) * (3 * Hc);
        ((float4*)Ks)[kp * 8 + d4] = *(const float4*)(qkv + row + Hc + head * DHc + d4 * 4);
        ((float4*)Vs)[kp * 8 + d4] = *(const float4*)(qkv + row + 2 * Hc + head * DHc + d4 * 4);
    }
    msk[tid] = g_mask[b * Mc + tid];
    __syncthreads();

    float qr[DHc];
    {
        const float* qp = qkv + (size_t)(b * Mc + tid) * (3 * Hc) + head * DHc;
#pragma unroll
        for (int d4 = 0; d4 < 8; d4++)
            *(float4*)&qr[d4 * 4] = *(const float4*)(qp + d4 * 4);
    }

    float mx = -3.0e38f, l = 0.f;
    float acc[DHc];
#pragma unroll
    for (int d = 0; d < DHc; d++) acc[d] = 0.f;

    const float scale = 0.17677669529663687f;
    for (int kp = 0; kp < Mc; kp++) {
        const float* kr = &Ks[kp * DHc];
        float s = 0.f;
#pragma unroll
        for (int d = 0; d < DHc; d++) s += qr[d] * kr[d];
        s *= scale;
        if (!msk[kp]) s = -1e9f;
        float mn = fmaxf(mx, s);
        float corr = fast_exp(mx - mn);
        float p = fast_exp(s - mn);
        l = l * corr + p;
        const float* vr = &Vs[kp * DHc];
#pragma unroll
        for (int d = 0; d < DHc; d++) acc[d] = acc[d] * corr + p * vr[d];
        mx = mn;
    }
    float inv = 1.f / l;
    float* op = g_adense + (size_t)(b * Mc + tid) * Hc + head * DHc;
#pragma unroll
    for (int d4 = 0; d4 < 8; d4++) {
        float4 o;
        o.x = acc[d4 * 4 + 0] * inv; o.y = acc[d4 * 4 + 1] * inv;
        o.z = acc[d4 * 4 + 2] * inv; o.w = acc[d4 * 4 + 3] * inv;
        *(float4*)(op + d4 * 4) = o;
    }
}

// ---------------- host orchestration ----------------
static inline int cdiv(long a, int b) { return (int)((a + b - 1) / b); }

extern "C" void kernel_launch(void* const* d_in, const int* in_sizes, int n_in,
                              void* d_out, int out_size) {
    const float* h         = (const float*)d_in[0];
    const float* gin_w1    = (const float*)d_in[1];
    const float* gin_b1    = (const float*)d_in[2];
    const float* gin_w2    = (const float*)d_in[3];
    const float* gin_b2    = (const float*)d_in[4];
    const float* in_proj_w = (const float*)d_in[5];
    const float* in_proj_b = (const float*)d_in[6];
    const float* out_proj_w= (const float*)d_in[7];
    const float* out_proj_b= (const float*)d_in[8];
    const float* bnl_g     = (const float*)d_in[9];
    const float* bnl_b     = (const float*)d_in[10];
    const float* bna_g     = (const float*)d_in[11];
    const float* bna_b     = (const float*)d_in[12];
    const float* bno_g     = (const float*)d_in[13];
    const float* bno_b     = (const float*)d_in[14];
    const float* ffn1_w    = (const float*)d_in[15];
    const float* ffn1_b    = (const float*)d_in[16];
    const float* ffn2_w    = (const float*)d_in[17];
    const float* ffn2_b    = (const float*)d_in[18];
    const int*   e_src     = (const int*)d_in[19];
    const int*   e_dst     = (const int*)d_in[20];
    const int*   bnn       = (const int*)d_in[21];

    const int nN = in_sizes[0] / Hc;      // 32768
    const int nE = in_sizes[19];          // 524288
    const int nB = in_sizes[21];          // 256
    const int n4 = nN * H4c;
    const float invN = 1.0f / (float)nN;

    float *p_agg, *p_z1, *p_pre, *p_hlocal, *p_hd, *p_qkv, *p_adense, *p_ao,
          *p_hh, *p_f1, *p_stats, *p_mask;
    __nv_bfloat16 *p_whi, *p_wlo;
    cudaGetSymbolAddress((void**)&p_agg,    g_agg);
    cudaGetSymbolAddress((void**)&p_z1,     g_z1);
    cudaGetSymbolAddress((void**)&p_pre,    g_pre);
    cudaGetSymbolAddress((void**)&p_hlocal, g_hlocal);
    cudaGetSymbolAddress((void**)&p_hd,     g_hd);
    cudaGetSymbolAddress((void**)&p_qkv,    g_qkv);
    cudaGetSymbolAddress((void**)&p_adense, g_adense);
    cudaGetSymbolAddress((void**)&p_ao,     g_ao);
    cudaGetSymbolAddress((void**)&p_hh,     g_hh);
    cudaGetSymbolAddress((void**)&p_f1,     g_f1);
    cudaGetSymbolAddress((void**)&p_stats,  g_stats);
    cudaGetSymbolAddress((void**)&p_mask,   g_mask);
    cudaGetSymbolAddress((void**)&p_whi,    g_whi);
    cudaGetSymbolAddress((void**)&p_wlo,    g_wlo);

    cudaFuncSetAttribute(mma_gemm<true>,  cudaFuncAttributeMaxDynamicSharedMemorySize, GEMM_SMEM);
    cudaFuncSetAttribute(mma_gemm<false>, cudaFuncAttributeMaxDynamicSharedMemorySize, GEMM_SMEM);

    // weight offsets in the split buffers (elements)
    const int OFF_GIN1 = 0;
    const int OFF_GIN2 = 65536;
    const int OFF_QKV  = 131072;
    const int OFF_OUT  = 327680;
    const int OFF_F1   = 393216;
    const int OFF_F2   = 524288;
    auto split = [&](const float* W, int off, int nelem) {
        wsplit_k<<<cdiv(nelem / 4, 256), 256>>>(W, p_whi + off, p_wlo + off, nelem / 4);
    };
    split(gin_w1,     OFF_GIN1, 65536);
    split(gin_w2,     OFF_GIN2, 65536);
    split(in_proj_w,  OFF_QKV,  196608);
    split(out_proj_w, OFF_OUT,  65536);
    split(ffn1_w,     OFF_F1,   131072);
    split(ffn2_w,     OFF_F2,   131072);

    auto gemm = [&](bool relu, const float* A, const float* A2, int woff,
                    const float* bias, const float* res, float* C, int Nc, int K) {
        dim3 grid(Nc / 128, nN / 128);
        if (relu)
            mma_gemm<true><<<grid, 256, GEMM_SMEM>>>(A, A2, p_whi + woff, p_wlo + woff,
                                                     bias, res, C, Nc, K);
        else
            mma_gemm<false><<<grid, 256, GEMM_SMEM>>>(A, A2, p_whi + woff, p_wlo + woff,
                                                      bias, res, C, Nc, K);
    };
    auto zero = [&](float* p, long nfloats) {
        int nn4 = (int)(nfloats / 4);
        zero_f4<<<cdiv(nn4, 256), 256>>>((float4*)p, nn4);
    };

    // ---- GIN local branch ----
    zero(p_agg, (long)nN * Hc);
    scatter_edges<<<cdiv((long)nE * H4c, 256), 256>>>(h, e_src, e_dst, nE);
    gemm(true,  h,    p_agg,   OFF_GIN1, gin_b1, nullptr, p_z1,  Hc, Hc);
    gemm(false, p_z1, nullptr, OFF_GIN2, gin_b2, h,       p_pre, Hc, Hc);
    zero(p_stats, 2 * Hc);
    bn_stats<<<nN / 128, Hc>>>(p_pre);
    bn_apply<<<cdiv(n4, 256), 256>>>(p_pre, bnl_g, bnl_b, nullptr, p_hlocal, invN, n4);

    // ---- dense batch scatter (of ORIGINAL h) ----
    scan_k<<<1, 256>>>(bnn, nB);
    idx_k<<<cdiv(nN, 256), 256>>>(nN, nB);
    zero(p_hd, (long)Bc * Mc * Hc);
    zero(p_mask, Bc * Mc);
    scatter_dense<<<cdiv((long)nN * H4c, 256), 256>>>(h, nN);
    set_mask<<<cdiv(nN, 256), 256>>>(nN);

    // ---- attention ----
    gemm(false, p_hd, nullptr, OFF_QKV, in_proj_b, nullptr, p_qkv, 3 * Hc, Hc);
    attn_k<<<Bc * NHc, Mc>>>();
    gemm(false, p_adense, nullptr, OFF_OUT, out_proj_b, nullptr, p_ao, Hc, Hc);
    gather_res<<<cdiv((long)nN * H4c, 256), 256>>>(h, nN);
    zero(p_stats, 2 * Hc);
    bn_stats<<<nN / 128, Hc>>>(p_pre);
    bn_apply<<<cdiv(n4, 256), 256>>>(p_pre, bna_g, bna_b, p_hlocal, p_hh, invN, n4);

    // ---- FFN + out norm ----
    gemm(true,  p_hh, nullptr, OFF_F1, ffn1_b, nullptr, p_f1,  2 * Hc, Hc);
    gemm(false, p_f1, nullptr, OFF_F2, ffn2_b, p_hh,    p_pre, Hc, 2 * Hc);
    zero(p_stats, 2 * Hc);
    bn_stats<<<nN / 128, Hc>>>(p_pre);
    bn_apply<<<cdiv(n4, 256), 256>>>(p_pre, bno_g, bno_b, nullptr, (float*)d_out, invN, n4);
}

// round 5
// speedup vs baseline: 1.6587x; 1.0813x over previous
#include <cuda_runtime.h>
#include <cuda_bf16.h>
#include <cuda_fp16.h>
#include <cstdint>
#include <cstdio>

// ---------------- problem constants ----------------
#define Hc   256
#define H4c  64
#define Bc   256
#define Mc   128
#define NHc  8
#define DHc  32
#define NMAX 32768

// ---------------- device scratch -------------------
__device__ float g_agg   [NMAX * Hc];
__device__ float g_z1    [NMAX * Hc];
__device__ float g_pre   [NMAX * Hc];     // pre_local
__device__ float g_hlocal[NMAX * Hc];     // pre_attn
__device__ float g_hd    [NMAX * Hc];     // pre_out
__device__ float g_qkv   [Bc * Mc * 3 * Hc];
__device__ float g_adense[Bc * Mc * Hc];
__device__ float g_hh    [NMAX * Hc];
__device__ float g_f1    [NMAX * 2 * Hc];
__device__ float g_bnstats[3 * 2 * Hc];   // 3 BNs x (sum[256], sq[256])
__device__ int   g_cum   [Bc + 1];
__device__ int   g_inv   [Bc * Mc];       // dense slot -> node (-1 pad)
__device__ int   g_mask  [Bc * Mc];
// pre-converted weights (fp16)
#define WTOT 655360
__device__ __align__(16) __half g_wh[WTOT];

// ---------------- PTX helpers ----------------------
__device__ __forceinline__ uint32_t smem_u32(const void* p) {
    uint32_t a;
    asm("{ .reg .u64 t; cvta.to.shared.u64 t, %1; cvt.u32.u64 %0, t; }"
        : "=r"(a) : "l"(p));
    return a;
}
#define LDSM_X4(r0, r1, r2, r3, addr)                                    \
    asm volatile("ldmatrix.sync.aligned.m8n8.x4.shared.b16 {%0,%1,%2,%3}, [%4];" \
                 : "=r"(r0), "=r"(r1), "=r"(r2), "=r"(r3) : "r"(addr))
#define MMA16816(d, a, b0, b1)                                           \
    asm volatile("mma.sync.aligned.m16n8k16.row.col.f32.f16.f16.f32 "    \
                 "{%0,%1,%2,%3}, {%4,%5,%6,%7}, {%8,%9}, {%0,%1,%2,%3};" \
                 : "+f"((d)[0]), "+f"((d)[1]), "+f"((d)[2]), "+f"((d)[3]) \
                 : "r"((a)[0]), "r"((a)[1]), "r"((a)[2]), "r"((a)[3]),   \
                   "r"(b0), "r"(b1))
#define CP_ASYNC16(dst, src)                                             \
    asm volatile("cp.async.ca.shared.global [%0], [%1], 16;" :: "r"(dst), "l"(src))
#define CP_COMMIT() asm volatile("cp.async.commit_group;")
#define CP_WAIT0()  asm volatile("cp.async.wait_group 0;" ::: "memory")

__device__ __forceinline__ uint32_t pack_h2(__half a, __half b) {
    __half2 p{a, b};
    return *(uint32_t*)&p;
}
__device__ __forceinline__ float ex2f(float x) {
    float y;
    asm("ex2.approx.ftz.f32 %0, %1;" : "=f"(y) : "f"(x));
    return y;
}

// ---------------- fp16 hi/lo mma GEMM (2 passes) ---
// C = act((A[+A2]) @ W^T + bias [+res]); A fp32 split to fp16 hi/lo in-kernel,
// W pre-converted fp16. Optional: a_inv (gather A rows), c_inv (scatter out rows
// + residual via res base + stats over valid rows), stats (BN sum/sumsq fusion).
#define ROWB 80
#define OFF_AHI 0
#define OFF_ALO 10240
#define OFF_B   20480
#define BUFSZ   30720
#define GEMM_SMEM (2 * BUFSZ)

template<bool RELU>
__global__ __launch_bounds__(256, 2)
void mma_gemm(const float* __restrict__ A, const float* __restrict__ A2,
              const int* __restrict__ a_inv,
              const __half* __restrict__ W, const float* __restrict__ bias,
              const float* __restrict__ res, const int* __restrict__ c_inv,
              float* __restrict__ C, float* __restrict__ stats,
              int Nc, int K) {
    extern __shared__ char smem[];
    const uint32_t sb = smem_u32(smem);
    const int tid = threadIdx.x;
    const int wid = tid >> 5, lane = tid & 31;
    const int wm = (wid >> 1) * 32, wn = (wid & 1) * 64;
    const int row0 = blockIdx.y * 128;
    const int col0 = blockIdx.x * 128;

    const int r = tid >> 1, half = tid & 1;

    // A row base for staging thread (constant across K iterations)
    const float* Abase;
    const float* A2base = nullptr;
    bool avalid = true;
    {
        int arow = row0 + r;
        if (a_inv) {
            int nd = a_inv[arow];
            avalid = nd >= 0;
            Abase = A + (size_t)(avalid ? nd : 0) * K;
        } else {
            Abase = A + (size_t)arow * K;
            if (A2) A2base = A2 + (size_t)arow * K;
        }
    }

    float acc[2][8][4];
#pragma unroll
    for (int mt = 0; mt < 2; mt++)
#pragma unroll
        for (int nt = 0; nt < 8; nt++)
#pragma unroll
            for (int q = 0; q < 4; q++) acc[mt][nt][q] = 0.f;

    const int nit = K >> 5;
    float4 va[4];

    // ---- prologue ----
    {
        const float* ap = Abase + half * 16;
        if (avalid) {
#pragma unroll
            for (int j = 0; j < 4; j++) va[j] = *(const float4*)(ap + j * 4);
            if (A2base) {
#pragma unroll
                for (int j = 0; j < 4; j++) {
                    float4 w = *(const float4*)(A2base + half * 16 + j * 4);
                    va[j].x += w.x; va[j].y += w.y; va[j].z += w.z; va[j].w += w.w;
                }
            }
        } else {
#pragma unroll
            for (int j = 0; j < 4; j++) va[j] = make_float4(0.f, 0.f, 0.f, 0.f);
        }
        const char* gb = (const char*)(W + (size_t)(col0 + r) * K + half * 16);
        uint32_t d0 = sb + OFF_B + r * ROWB + half * 32;
        CP_ASYNC16(d0, gb); CP_ASYNC16(d0 + 16, gb + 16);
        CP_COMMIT();
    }

    for (int i = 0; i < nit; i++) {
        const uint32_t boff = (uint32_t)(i & 1) * BUFSZ;
        // convert + STS A tile
        {
            uint32_t hv[8], lv[8];
#pragma unroll
            for (int j = 0; j < 4; j++) {
                float4 v = va[j];
                __half hx = __float2half_rn(v.x), hy = __float2half_rn(v.y);
                __half hz = __float2half_rn(v.z), hw = __float2half_rn(v.w);
                hv[j * 2 + 0] = pack_h2(hx, hy);
                hv[j * 2 + 1] = pack_h2(hz, hw);
                lv[j * 2 + 0] = pack_h2(__float2half_rn(v.x - __half2float(hx)),
                                        __float2half_rn(v.y - __half2float(hy)));
                lv[j * 2 + 1] = pack_h2(__float2half_rn(v.z - __half2float(hz)),
                                        __float2half_rn(v.w - __half2float(hw)));
            }
            char* pa = smem + boff + OFF_AHI + r * ROWB + half * 32;
            *(uint4*)pa = *(uint4*)&hv[0];
            *(uint4*)(pa + 16) = *(uint4*)&hv[4];
            char* pl = smem + boff + OFF_ALO + r * ROWB + half * 32;
            *(uint4*)pl = *(uint4*)&lv[0];
            *(uint4*)(pl + 16) = *(uint4*)&lv[4];
        }
        CP_WAIT0();
        __syncthreads();
        // prefetch next tile
        if (i + 1 < nit) {
            const int k0 = (i + 1) * 32;
            if (avalid) {
                const float* ap = Abase + k0 + half * 16;
#pragma unroll
                for (int j = 0; j < 4; j++) va[j] = *(const float4*)(ap + j * 4);
                if (A2base) {
#pragma unroll
                    for (int j = 0; j < 4; j++) {
                        float4 w = *(const float4*)(A2base + k0 + half * 16 + j * 4);
                        va[j].x += w.x; va[j].y += w.y; va[j].z += w.z; va[j].w += w.w;
                    }
                }
            }
            const uint32_t nb = (uint32_t)((i + 1) & 1) * BUFSZ;
            const char* gb = (const char*)(W + (size_t)(col0 + r) * K + k0 + half * 16);
            uint32_t d0 = sb + nb + OFF_B + r * ROWB + half * 32;
            CP_ASYNC16(d0, gb); CP_ASYNC16(d0 + 16, gb + 16);
            CP_COMMIT();
        }
        // mma on current tile
#pragma unroll
        for (int ks = 0; ks < 2; ks++) {
            uint32_t ah[2][4], al[2][4];
#pragma unroll
            for (int mt = 0; mt < 2; mt++) {
                uint32_t arow = wm + mt * 16 + (lane & 15);
                uint32_t kb = ks * 32 + ((lane >> 4) * 16);
                uint32_t ad = sb + boff + OFF_AHI + arow * ROWB + kb;
                LDSM_X4(ah[mt][0], ah[mt][1], ah[mt][2], ah[mt][3], ad);
                LDSM_X4(al[mt][0], al[mt][1], al[mt][2], al[mt][3],
                        ad + (OFF_ALO - OFF_AHI));
            }
#pragma unroll
            for (int np = 0; np < 4; np++) {
                uint32_t nrow = wn + np * 16 + ((lane >> 4) << 3) + (lane & 7);
                uint32_t kb = ks * 32 + (((lane >> 3) & 1) << 4);
                uint32_t bd = sb + boff + OFF_B + nrow * ROWB + kb;
                uint32_t bh[4];
                LDSM_X4(bh[0], bh[1], bh[2], bh[3], bd);
#pragma unroll
                for (int mt = 0; mt < 2; mt++) {
                    MMA16816(acc[mt][2 * np],     ah[mt], bh[0], bh[1]);
                    MMA16816(acc[mt][2 * np],     al[mt], bh[0], bh[1]);
                    MMA16816(acc[mt][2 * np + 1], ah[mt], bh[2], bh[3]);
                    MMA16816(acc[mt][2 * np + 1], al[mt], bh[2], bh[3]);
                }
            }
        }
    }

    // ---- epilogue ----
    __syncthreads();   // allow smem reuse for stats
    float* ssum = (float*)smem;
    float* ssq  = ssum + 128;
    if (stats) {
        if (tid < 128) { ssum[tid] = 0.f; ssq[tid] = 0.f; }
        __syncthreads();
    }
    int rA0 = row0 + wm + (lane >> 2);
    int nmap[2][2];
    if (c_inv) {
        nmap[0][0] = c_inv[rA0];      nmap[0][1] = c_inv[rA0 + 8];
        nmap[1][0] = c_inv[rA0 + 16]; nmap[1][1] = c_inv[rA0 + 24];
    }
#pragma unroll
    for (int nt = 0; nt < 8; nt++) {
        int c = col0 + wn + nt * 8 + (lane & 3) * 2;
        float2 bi = *(const float2*)(bias + c);
        float cs0 = 0.f, cs1 = 0.f, cq0 = 0.f, cq1 = 0.f;
#pragma unroll
        for (int mt = 0; mt < 2; mt++) {
            int ra = rA0 + mt * 16;
            float o0 = acc[mt][nt][0] + bi.x, o1 = acc[mt][nt][1] + bi.y;
            float o2 = acc[mt][nt][2] + bi.x, o3 = acc[mt][nt][3] + bi.y;
            if (c_inv) {
                int na = nmap[mt][0], nb = nmap[mt][1];
                if (na >= 0) {
                    float2 rv = *(const float2*)(res + (size_t)na * Nc + c);
                    o0 += rv.x; o1 += rv.y;
                    *(float2*)(C + (size_t)na * Nc + c) = make_float2(o0, o1);
                    cs0 += o0; cq0 += o0 * o0; cs1 += o1; cq1 += o1 * o1;
                }
                if (nb >= 0) {
                    float2 rv = *(const float2*)(res + (size_t)nb * Nc + c);
                    o2 += rv.x; o3 += rv.y;
                    *(float2*)(C + (size_t)nb * Nc + c) = make_float2(o2, o3);
                    cs0 += o2; cq0 += o2 * o2; cs1 += o3; cq1 += o3 * o3;
                }
            } else {
                if (res) {
                    float2 r0 = *(const float2*)(res + (size_t)ra * Nc + c);
                    float2 r1 = *(const float2*)(res + (size_t)(ra + 8) * Nc + c);
                    o0 += r0.x; o1 += r0.y; o2 += r1.x; o3 += r1.y;
                }
                if (RELU) {
                    o0 = fmaxf(o0, 0.f); o1 = fmaxf(o1, 0.f);
                    o2 = fmaxf(o2, 0.f); o3 = fmaxf(o3, 0.f);
                }
                *(float2*)(C + (size_t)ra * Nc + c) = make_float2(o0, o1);
                *(float2*)(C + (size_t)(ra + 8) * Nc + c) = make_float2(o2, o3);
                if (stats) {
                    cs0 += o0 + o2; cq0 += o0 * o0 + o2 * o2;
                    cs1 += o1 + o3; cq1 += o1 * o1 + o3 * o3;
                }
            }
        }
        if (stats) {
            int lc = c - col0;
            atomicAdd(&ssum[lc], cs0); atomicAdd(&ssq[lc], cq0);
            atomicAdd(&ssum[lc + 1], cs1); atomicAdd(&ssq[lc + 1], cq1);
        }
    }
    if (stats) {
        __syncthreads();
        if (tid < 128) {
            atomicAdd(&stats[col0 + tid], ssum[tid]);
            atomicAdd(&stats[Hc + col0 + tid], ssq[tid]);
        }
    }
}

// weight convert prepass: fp32 -> fp16
__global__ void wsplit_k(const float* __restrict__ W, __half* __restrict__ wh, int n4) {
    int i = blockIdx.x * 256 + threadIdx.x;
    if (i >= n4) return;
    float4 v = ((const float4*)W)[i];
    ((uint2*)wh)[i] = make_uint2(
        pack_h2(__float2half_rn(v.x), __float2half_rn(v.y)),
        pack_h2(__float2half_rn(v.z), __float2half_rn(v.w)));
}

// ---------------- utility kernels ------------------
__global__ void zero_f4(float4* p, int n4) {
    int i = blockIdx.x * 256 + threadIdx.x;
    if (i < n4) p[i] = make_float4(0.f, 0.f, 0.f, 0.f);
}

__global__ void scatter_edges(const float* __restrict__ h,
                              const int* __restrict__ src,
                              const int* __restrict__ dst, int E) {
    long gid = (long)blockIdx.x * 256 + threadIdx.x;
    if (gid >= (long)E * H4c) return;
    int e = (int)(gid >> 6);
    int c = (int)(gid & 63);
    int s = __ldg(&src[e]);
    int d = __ldg(&dst[e]);
    float4 v = ((const float4*)h)[(size_t)s * H4c + c];
    float4* p = ((float4*)g_agg) + (size_t)d * H4c + c;
    asm volatile("red.global.add.v4.f32 [%0], {%1,%2,%3,%4};"
                 :: "l"(p), "f"(v.x), "f"(v.y), "f"(v.z), "f"(v.w) : "memory");
}

__global__ void scan_k(const int* __restrict__ bnn, int B) {
    __shared__ int sm[256];
    int t = threadIdx.x;
    sm[t] = (t < B) ? bnn[t] : 0;
    __syncthreads();
    for (int off = 1; off < 256; off <<= 1) {
        int v = sm[t] + ((t >= off) ? sm[t - off] : 0);
        __syncthreads();
        sm[t] = v;
        __syncthreads();
    }
    if (t == 0) g_cum[0] = 0;
    if (t < B) g_cum[t + 1] = sm[t];
}

__global__ void inv_k(const int* __restrict__ bnn) {
    int s = blockIdx.x * 256 + threadIdx.x;
    if (s >= Bc * Mc) return;
    int b = s >> 7, rr = s & (Mc - 1);
    bool v = rr < bnn[b];
    g_inv[s] = v ? (g_cum[b] + rr) : -1;
    g_mask[s] = v ? 1 : 0;
}

// bn for given stats: g*(x-m)*rsqrt(v+eps)+b
__device__ __forceinline__ float4 bn4(float4 x, float4 s, float4 q,
                                      float4 g, float4 b, float invN) {
    float4 o;
    { float m = s.x * invN, v = q.x * invN - m * m; o.x = g.x * (x.x - m) * rsqrtf(v + 1e-5f) + b.x; }
    { float m = s.y * invN, v = q.y * invN - m * m; o.y = g.y * (x.y - m) * rsqrtf(v + 1e-5f) + b.y; }
    { float m = s.z * invN, v = q.z * invN - m * m; o.z = g.z * (x.z - m) * rsqrtf(v + 1e-5f) + b.z; }
    { float m = s.w * invN, v = q.w * invN - m * m; o.w = g.w * (x.w - m) * rsqrtf(v + 1e-5f) + b.w; }
    return o;
}

// hh = bn_local(pre_local) + bn_attn(pre_attn)
__global__ void bn_combine(const float* __restrict__ PL, const float* __restrict__ PA,
                           const float* __restrict__ gl, const float* __restrict__ bl,
                           const float* __restrict__ ga, const float* __restrict__ ba,
                           const float* __restrict__ stl, const float* __restrict__ sta,
                           float* __restrict__ out, float invN, int n4tot) {
    int gid = blockIdx.x * 256 + threadIdx.x;
    if (gid >= n4tot) return;
    int c4 = gid & 63;
    float4 a = bn4(((const float4*)PL)[gid], ((const float4*)stl)[c4],
                   ((const float4*)stl)[H4c + c4], ((const float4*)gl)[c4],
                   ((const float4*)bl)[c4], invN);
    float4 b = bn4(((const float4*)PA)[gid], ((const float4*)sta)[c4],
                   ((const float4*)sta)[H4c + c4], ((const float4*)ga)[c4],
                   ((const float4*)ba)[c4], invN);
    a.x += b.x; a.y += b.y; a.z += b.z; a.w += b.w;
    ((float4*)out)[gid] = a;
}

__global__ void bn_apply(const float* __restrict__ X, const float* __restrict__ st,
                         const float* __restrict__ gamma, const float* __restrict__ beta,
                         float* __restrict__ out, float invN, int n4total) {
    int gid = blockIdx.x * 256 + threadIdx.x;
    if (gid >= n4total) return;
    int c4 = gid & 63;
    float4 o = bn4(((const float4*)X)[gid], ((const float4*)st)[c4],
                   ((const float4*)st)[H4c + c4], ((const float4*)gamma)[c4],
                   ((const float4*)beta)[c4], invN);
    ((float4*)out)[gid] = o;
}

// ---------------- attention ------------------------
__global__ __launch_bounds__(128)
void attn_k() {
    int b = blockIdx.x / NHc;
    int head = blockIdx.x % NHc;
    __shared__ float Ks[Mc * DHc];
    __shared__ float Vs[Mc * DHc];
    __shared__ int msk[Mc];
    int tid = threadIdx.x;

    const float* qkv = g_qkv;
#pragma unroll
    for (int i = 0; i < 8; i++) {
        int id = tid + i * 128;
        int kp = id >> 3, d4 = id & 7;
        size_t row = (size_t)(b * Mc + kp) * (3 * Hc);
        ((float4*)Ks)[kp * 8 + d4] = *(const float4*)(qkv + row + Hc + head * DHc + d4 * 4);
        ((float4*)Vs)[kp * 8 + d4] = *(const float4*)(qkv + row + 2 * Hc + head * DHc + d4 * 4);
    }
    msk[tid] = g_mask[b * Mc + tid];
    __syncthreads();

    float qr[DHc];
    {
        const float* qp = qkv + (size_t)(b * Mc + tid) * (3 * Hc) + head * DHc;
#pragma unroll
        for (int d4 = 0; d4 < 8; d4++)
            *(float4*)&qr[d4 * 4] = *(const float4*)(qp + d4 * 4);
    }

    float mx = -3.0e38f, l = 0.f;
    float acc[DHc];
#pragma unroll
    for (int d = 0; d < DHc; d++) acc[d] = 0.f;

    // base-2 softmax: scale * log2(e)
    const float sc2 = 0.17677669529663687f * 1.44269504088896341f;
    for (int kp = 0; kp < Mc; kp++) {
        const float* kr = &Ks[kp * DHc];
        float s = 0.f;
#pragma unroll
        for (int d = 0; d < DHc; d++) s += qr[d] * kr[d];
        s *= sc2;
        if (!msk[kp]) s = -1e30f;
        float mn = fmaxf(mx, s);
        float corr = ex2f(mx - mn);
        float p = ex2f(s - mn);
        l = l * corr + p;
        const float* vr = &Vs[kp * DHc];
#pragma unroll
        for (int d = 0; d < DHc; d++) acc[d] = acc[d] * corr + p * vr[d];
        mx = mn;
    }
    float inv = 1.f / l;
    float* op = g_adense + (size_t)(b * Mc + tid) * Hc + head * DHc;
#pragma unroll
    for (int d4 = 0; d4 < 8; d4++) {
        float4 o;
        o.x = acc[d4 * 4 + 0] * inv; o.y = acc[d4 * 4 + 1] * inv;
        o.z = acc[d4 * 4 + 2] * inv; o.w = acc[d4 * 4 + 3] * inv;
        *(float4*)(op + d4 * 4) = o;
    }
}

// ---------------- host orchestration ----------------
static inline int cdiv(long a, int b) { return (int)((a + b - 1) / b); }

extern "C" void kernel_launch(void* const* d_in, const int* in_sizes, int n_in,
                              void* d_out, int out_size) {
    const float* h         = (const float*)d_in[0];
    const float* gin_w1    = (const float*)d_in[1];
    const float* gin_b1    = (const float*)d_in[2];
    const float* gin_w2    = (const float*)d_in[3];
    const float* gin_b2    = (const float*)d_in[4];
    const float* in_proj_w = (const float*)d_in[5];
    const float* in_proj_b = (const float*)d_in[6];
    const float* out_proj_w= (const float*)d_in[7];
    const float* out_proj_b= (const float*)d_in[8];
    const float* bnl_g     = (const float*)d_in[9];
    const float* bnl_b     = (const float*)d_in[10];
    const float* bna_g     = (const float*)d_in[11];
    const float* bna_b     = (const float*)d_in[12];
    const float* bno_g     = (const float*)d_in[13];
    const float* bno_b     = (const float*)d_in[14];
    const float* ffn1_w    = (const float*)d_in[15];
    const float* ffn1_b    = (const float*)d_in[16];
    const float* ffn2_w    = (const float*)d_in[17];
    const float* ffn2_b    = (const float*)d_in[18];
    const int*   e_src     = (const int*)d_in[19];
    const int*   e_dst     = (const int*)d_in[20];
    const int*   bnn       = (const int*)d_in[21];

    const int nN = in_sizes[0] / Hc;      // 32768
    const int nE = in_sizes[19];          // 524288
    const int nB = in_sizes[21];          // 256
    const int n4 = nN * H4c;
    const float invN = 1.0f / (float)nN;

    float *p_agg, *p_z1, *p_PL, *p_PA, *p_PO, *p_qkv, *p_adense, *p_hh, *p_f1, *p_st;
    int *p_inv;
    __half* p_wh;
    cudaGetSymbolAddress((void**)&p_agg,    g_agg);
    cudaGetSymbolAddress((void**)&p_z1,     g_z1);
    cudaGetSymbolAddress((void**)&p_PL,     g_pre);
    cudaGetSymbolAddress((void**)&p_PA,     g_hlocal);
    cudaGetSymbolAddress((void**)&p_PO,     g_hd);
    cudaGetSymbolAddress((void**)&p_qkv,    g_qkv);
    cudaGetSymbolAddress((void**)&p_adense, g_adense);
    cudaGetSymbolAddress((void**)&p_hh,     g_hh);
    cudaGetSymbolAddress((void**)&p_f1,     g_f1);
    cudaGetSymbolAddress((void**)&p_st,     g_bnstats);
    cudaGetSymbolAddress((void**)&p_inv,    g_inv);
    cudaGetSymbolAddress((void**)&p_wh,     g_wh);

    float* st_l = p_st;
    float* st_a = p_st + 2 * Hc;
    float* st_o = p_st + 4 * Hc;

    cudaFuncSetAttribute(mma_gemm<true>,  cudaFuncAttributeMaxDynamicSharedMemorySize, GEMM_SMEM);
    cudaFuncSetAttribute(mma_gemm<false>, cudaFuncAttributeMaxDynamicSharedMemorySize, GEMM_SMEM);

    const int OFF_GIN1 = 0;
    const int OFF_GIN2 = 65536;
    const int OFF_QKV  = 131072;
    const int OFF_OUT  = 327680;
    const int OFF_F1   = 393216;
    const int OFF_F2   = 524288;
    auto split = [&](const float* W, int off, int nelem) {
        wsplit_k<<<cdiv(nelem / 4, 256), 256>>>(W, p_wh + off, nelem / 4);
    };
    split(gin_w1,     OFF_GIN1, 65536);
    split(gin_w2,     OFF_GIN2, 65536);
    split(in_proj_w,  OFF_QKV,  196608);
    split(out_proj_w, OFF_OUT,  65536);
    split(ffn1_w,     OFF_F1,   131072);
    split(ffn2_w,     OFF_F2,   131072);

    auto gemm = [&](bool relu, const float* A, const float* A2, const int* a_inv,
                    int woff, const float* bias, const float* res, const int* c_inv,
                    float* C, float* stats, int Nc, int K) {
        dim3 grid(Nc / 128, nN / 128);
        if (relu)
            mma_gemm<true><<<grid, 256, GEMM_SMEM>>>(A, A2, a_inv, p_wh + woff,
                                                     bias, res, c_inv, C, stats, Nc, K);
        else
            mma_gemm<false><<<grid, 256, GEMM_SMEM>>>(A, A2, a_inv, p_wh + woff,
                                                      bias, res, c_inv, C, stats, Nc, K);
    };
    auto zero = [&](float* p, long nfloats) {
        int nn4 = (int)(nfloats / 4);
        zero_f4<<<cdiv(nn4, 256), 256>>>((float4*)p, nn4);
    };

    // ---- prep: stats zero, agg zero, edge scatter, dense-batch index ----
    zero(p_st, 6 * Hc);
    zero(p_agg, (long)nN * Hc);
    scatter_edges<<<cdiv((long)nE * H4c, 256), 256>>>(h, e_src, e_dst, nE);
    scan_k<<<1, 256>>>(bnn, nB);
    inv_k<<<cdiv(Bc * Mc, 256), 256>>>(bnn);

    // ---- GIN local branch (stats fused into gin2 epilogue) ----
    gemm(true,  h,    p_agg,   nullptr, OFF_GIN1, gin_b1, nullptr, nullptr, p_z1, nullptr, Hc, Hc);
    gemm(false, p_z1, nullptr, nullptr, OFF_GIN2, gin_b2, h,       nullptr, p_PL, st_l,    Hc, Hc);

    // ---- attention branch ----
    // qkv: A gathered via inv (dense rows), from ORIGINAL h
    gemm(false, h, nullptr, p_inv, OFF_QKV, in_proj_b, nullptr, nullptr, p_qkv, nullptr, 3 * Hc, Hc);
    attn_k<<<Bc * NHc, Mc>>>();
    // out_proj: output scattered back to node space + residual h + stats fused
    gemm(false, p_adense, nullptr, nullptr, OFF_OUT, out_proj_b, h, p_inv, p_PA, st_a, Hc, Hc);

    // ---- combine both BNs -> hh ----
    bn_combine<<<cdiv(n4, 256), 256>>>(p_PL, p_PA, bnl_g, bnl_b, bna_g, bna_b,
                                       st_l, st_a, p_hh, invN, n4);

    // ---- FFN (stats fused into ffn2 epilogue) + final norm ----
    gemm(true,  p_hh, nullptr, nullptr, OFF_F1, ffn1_b, nullptr, nullptr, p_f1, nullptr, 2 * Hc, Hc);
    gemm(false, p_f1, nullptr, nullptr, OFF_F2, ffn2_b, p_hh,    nullptr, p_PO, st_o,    Hc, 2 * Hc);
    bn_apply<<<cdiv(n4, 256), 256>>>(p_PO, st_o, bno_g, bno_b, (float*)d_out, invN, n4);
}

// round 6
// speedup vs baseline: 2.0198x; 1.2177x over previous
#include <cuda_runtime.h>
#include <cuda_bf16.h>
#include <cuda_fp16.h>
#include <cstdint>
#include <cstdio>

// ---------------- problem constants ----------------
#define Hc   256
#define H4c  64
#define Bc   256
#define Mc   128
#define NHc  8
#define DHc  32
#define NMAX 32768

// ---------------- device scratch -------------------
__device__ float g_agg   [NMAX * Hc];
__device__ float g_z1    [NMAX * Hc];
__device__ float g_pre   [NMAX * Hc];     // pre_local
__device__ float g_hlocal[NMAX * Hc];     // pre_attn
__device__ float g_hd    [NMAX * Hc];     // pre_out
__device__ float g_qkv   [Bc * Mc * 3 * Hc];
__device__ float g_adense[Bc * Mc * Hc];
__device__ float g_hh    [NMAX * Hc];
__device__ float g_f1    [NMAX * 2 * Hc];
__device__ float g_bnstats[3 * 2 * Hc];
__device__ int   g_inv   [Bc * Mc];
__device__ int   g_mask  [Bc * Mc];
#define WTOT 655360
__device__ __align__(16) __half g_wh[WTOT];

// ---------------- PTX helpers ----------------------
__device__ __forceinline__ uint32_t smem_u32(const void* p) {
    uint32_t a;
    asm("{ .reg .u64 t; cvta.to.shared.u64 t, %1; cvt.u32.u64 %0, t; }"
        : "=r"(a) : "l"(p));
    return a;
}
#define LDSM_X4(r0, r1, r2, r3, addr)                                    \
    asm volatile("ldmatrix.sync.aligned.m8n8.x4.shared.b16 {%0,%1,%2,%3}, [%4];" \
                 : "=r"(r0), "=r"(r1), "=r"(r2), "=r"(r3) : "r"(addr))
#define MMA16816(d, a, b0, b1)                                           \
    asm volatile("mma.sync.aligned.m16n8k16.row.col.f32.f16.f16.f32 "    \
                 "{%0,%1,%2,%3}, {%4,%5,%6,%7}, {%8,%9}, {%0,%1,%2,%3};" \
                 : "+f"((d)[0]), "+f"((d)[1]), "+f"((d)[2]), "+f"((d)[3]) \
                 : "r"((a)[0]), "r"((a)[1]), "r"((a)[2]), "r"((a)[3]),   \
                   "r"(b0), "r"(b1))
#define CP_ASYNC16(dst, src)                                             \
    asm volatile("cp.async.ca.shared.global [%0], [%1], 16;" :: "r"(dst), "l"(src))
#define CP_COMMIT() asm volatile("cp.async.commit_group;")
#define CP_WAIT0()  asm volatile("cp.async.wait_group 0;" ::: "memory")

__device__ __forceinline__ uint32_t pack_h2(__half a, __half b) {
    __half2 p{a, b};
    return *(uint32_t*)&p;
}
__device__ __forceinline__ uint32_t pack_f2h(float a, float b) {
    return pack_h2(__float2half_rn(a), __float2half_rn(b));
}
__device__ __forceinline__ float ex2f(float x) {
    float y;
    asm("ex2.approx.ftz.f32 %0, %1;" : "=f"(y) : "f"(x));
    return y;
}

// ---------------- fp16 hi/lo mma GEMM (unchanged from R5) ---------------
#define ROWB 80
#define OFF_AHI 0
#define OFF_ALO 10240
#define OFF_B   20480
#define BUFSZ   30720
#define GEMM_SMEM (2 * BUFSZ)

template<bool RELU>
__global__ __launch_bounds__(256, 2)
void mma_gemm(const float* __restrict__ A, const float* __restrict__ A2,
              const int* __restrict__ a_inv,
              const __half* __restrict__ W, const float* __restrict__ bias,
              const float* __restrict__ res, const int* __restrict__ c_inv,
              float* __restrict__ C, float* __restrict__ stats,
              int Nc, int K) {
    extern __shared__ char smem[];
    const uint32_t sb = smem_u32(smem);
    const int tid = threadIdx.x;
    const int wid = tid >> 5, lane = tid & 31;
    const int wm = (wid >> 1) * 32, wn = (wid & 1) * 64;
    const int row0 = blockIdx.y * 128;
    const int col0 = blockIdx.x * 128;

    const int r = tid >> 1, half = tid & 1;

    const float* Abase;
    const float* A2base = nullptr;
    bool avalid = true;
    {
        int arow = row0 + r;
        if (a_inv) {
            int nd = a_inv[arow];
            avalid = nd >= 0;
            Abase = A + (size_t)(avalid ? nd : 0) * K;
        } else {
            Abase = A + (size_t)arow * K;
            if (A2) A2base = A2 + (size_t)arow * K;
        }
    }

    float acc[2][8][4];
#pragma unroll
    for (int mt = 0; mt < 2; mt++)
#pragma unroll
        for (int nt = 0; nt < 8; nt++)
#pragma unroll
            for (int q = 0; q < 4; q++) acc[mt][nt][q] = 0.f;

    const int nit = K >> 5;
    float4 va[4];

    {
        const float* ap = Abase + half * 16;
        if (avalid) {
#pragma unroll
            for (int j = 0; j < 4; j++) va[j] = *(const float4*)(ap + j * 4);
            if (A2base) {
#pragma unroll
                for (int j = 0; j < 4; j++) {
                    float4 w = *(const float4*)(A2base + half * 16 + j * 4);
                    va[j].x += w.x; va[j].y += w.y; va[j].z += w.z; va[j].w += w.w;
                }
            }
        } else {
#pragma unroll
            for (int j = 0; j < 4; j++) va[j] = make_float4(0.f, 0.f, 0.f, 0.f);
        }
        const char* gb = (const char*)(W + (size_t)(col0 + r) * K + half * 16);
        uint32_t d0 = sb + OFF_B + r * ROWB + half * 32;
        CP_ASYNC16(d0, gb); CP_ASYNC16(d0 + 16, gb + 16);
        CP_COMMIT();
    }

    for (int i = 0; i < nit; i++) {
        const uint32_t boff = (uint32_t)(i & 1) * BUFSZ;
        {
            uint32_t hv[8], lv[8];
#pragma unroll
            for (int j = 0; j < 4; j++) {
                float4 v = va[j];
                __half hx = __float2half_rn(v.x), hy = __float2half_rn(v.y);
                __half hz = __float2half_rn(v.z), hw = __float2half_rn(v.w);
                hv[j * 2 + 0] = pack_h2(hx, hy);
                hv[j * 2 + 1] = pack_h2(hz, hw);
                lv[j * 2 + 0] = pack_h2(__float2half_rn(v.x - __half2float(hx)),
                                        __float2half_rn(v.y - __half2float(hy)));
                lv[j * 2 + 1] = pack_h2(__float2half_rn(v.z - __half2float(hz)),
                                        __float2half_rn(v.w - __half2float(hw)));
            }
            char* pa = smem + boff + OFF_AHI + r * ROWB + half * 32;
            *(uint4*)pa = *(uint4*)&hv[0];
            *(uint4*)(pa + 16) = *(uint4*)&hv[4];
            char* pl = smem + boff + OFF_ALO + r * ROWB + half * 32;
            *(uint4*)pl = *(uint4*)&lv[0];
            *(uint4*)(pl + 16) = *(uint4*)&lv[4];
        }
        CP_WAIT0();
        __syncthreads();
        if (i + 1 < nit) {
            const int k0 = (i + 1) * 32;
            if (avalid) {
                const float* ap = Abase + k0 + half * 16;
#pragma unroll
                for (int j = 0; j < 4; j++) va[j] = *(const float4*)(ap + j * 4);
                if (A2base) {
#pragma unroll
                    for (int j = 0; j < 4; j++) {
                        float4 w = *(const float4*)(A2base + k0 + half * 16 + j * 4);
                        va[j].x += w.x; va[j].y += w.y; va[j].z += w.z; va[j].w += w.w;
                    }
                }
            }
            const uint32_t nb = (uint32_t)((i + 1) & 1) * BUFSZ;
            const char* gb = (const char*)(W + (size_t)(col0 + r) * K + k0 + half * 16);
            uint32_t d0 = sb + nb + OFF_B + r * ROWB + half * 32;
            CP_ASYNC16(d0, gb); CP_ASYNC16(d0 + 16, gb + 16);
            CP_COMMIT();
        }
#pragma unroll
        for (int ks = 0; ks < 2; ks++) {
            uint32_t ah[2][4], al[2][4];
#pragma unroll
            for (int mt = 0; mt < 2; mt++) {
                uint32_t arow = wm + mt * 16 + (lane & 15);
                uint32_t kb = ks * 32 + ((lane >> 4) * 16);
                uint32_t ad = sb + boff + OFF_AHI + arow * ROWB + kb;
                LDSM_X4(ah[mt][0], ah[mt][1], ah[mt][2], ah[mt][3], ad);
                LDSM_X4(al[mt][0], al[mt][1], al[mt][2], al[mt][3],
                        ad + (OFF_ALO - OFF_AHI));
            }
#pragma unroll
            for (int np = 0; np < 4; np++) {
                uint32_t nrow = wn + np * 16 + ((lane >> 4) << 3) + (lane & 7);
                uint32_t kb = ks * 32 + (((lane >> 3) & 1) << 4);
                uint32_t bd = sb + boff + OFF_B + nrow * ROWB + kb;
                uint32_t bh[4];
                LDSM_X4(bh[0], bh[1], bh[2], bh[3], bd);
#pragma unroll
                for (int mt = 0; mt < 2; mt++) {
                    MMA16816(acc[mt][2 * np],     ah[mt], bh[0], bh[1]);
                    MMA16816(acc[mt][2 * np],     al[mt], bh[0], bh[1]);
                    MMA16816(acc[mt][2 * np + 1], ah[mt], bh[2], bh[3]);
                    MMA16816(acc[mt][2 * np + 1], al[mt], bh[2], bh[3]);
                }
            }
        }
    }

    __syncthreads();
    float* ssum = (float*)smem;
    float* ssq  = ssum + 128;
    if (stats) {
        if (tid < 128) { ssum[tid] = 0.f; ssq[tid] = 0.f; }
        __syncthreads();
    }
    int rA0 = row0 + wm + (lane >> 2);
    int nmap[2][2];
    if (c_inv) {
        nmap[0][0] = c_inv[rA0];      nmap[0][1] = c_inv[rA0 + 8];
        nmap[1][0] = c_inv[rA0 + 16]; nmap[1][1] = c_inv[rA0 + 24];
    }
#pragma unroll
    for (int nt = 0; nt < 8; nt++) {
        int c = col0 + wn + nt * 8 + (lane & 3) * 2;
        float2 bi = *(const float2*)(bias + c);
        float cs0 = 0.f, cs1 = 0.f, cq0 = 0.f, cq1 = 0.f;
#pragma unroll
        for (int mt = 0; mt < 2; mt++) {
            int ra = rA0 + mt * 16;
            float o0 = acc[mt][nt][0] + bi.x, o1 = acc[mt][nt][1] + bi.y;
            float o2 = acc[mt][nt][2] + bi.x, o3 = acc[mt][nt][3] + bi.y;
            if (c_inv) {
                int na = nmap[mt][0], nb = nmap[mt][1];
                if (na >= 0) {
                    float2 rv = *(const float2*)(res + (size_t)na * Nc + c);
                    o0 += rv.x; o1 += rv.y;
                    *(float2*)(C + (size_t)na * Nc + c) = make_float2(o0, o1);
                    cs0 += o0; cq0 += o0 * o0; cs1 += o1; cq1 += o1 * o1;
                }
                if (nb >= 0) {
                    float2 rv = *(const float2*)(res + (size_t)nb * Nc + c);
                    o2 += rv.x; o3 += rv.y;
                    *(float2*)(C + (size_t)nb * Nc + c) = make_float2(o2, o3);
                    cs0 += o2; cq0 += o2 * o2; cs1 += o3; cq1 += o3 * o3;
                }
            } else {
                if (res) {
                    float2 r0 = *(const float2*)(res + (size_t)ra * Nc + c);
                    float2 r1 = *(const float2*)(res + (size_t)(ra + 8) * Nc + c);
                    o0 += r0.x; o1 += r0.y; o2 += r1.x; o3 += r1.y;
                }
                if (RELU) {
                    o0 = fmaxf(o0, 0.f); o1 = fmaxf(o1, 0.f);
                    o2 = fmaxf(o2, 0.f); o3 = fmaxf(o3, 0.f);
                }
                *(float2*)(C + (size_t)ra * Nc + c) = make_float2(o0, o1);
                *(float2*)(C + (size_t)(ra + 8) * Nc + c) = make_float2(o2, o3);
                if (stats) {
                    cs0 += o0 + o2; cq0 += o0 * o0 + o2 * o2;
                    cs1 += o1 + o3; cq1 += o1 * o1 + o3 * o3;
                }
            }
        }
        if (stats) {
            int lc = c - col0;
            atomicAdd(&ssum[lc], cs0); atomicAdd(&ssq[lc], cq0);
            atomicAdd(&ssum[lc + 1], cs1); atomicAdd(&ssq[lc + 1], cq1);
        }
    }
    if (stats) {
        __syncthreads();
        if (tid < 128) {
            atomicAdd(&stats[col0 + tid], ssum[tid]);
            atomicAdd(&stats[Hc + col0 + tid], ssq[tid]);
        }
    }
}

// ---------------- single-launch weight convert ------
__global__ void wsplit_all(const float* w0, const float* w1, const float* w2,
                           const float* w3, const float* w4, const float* w5) {
    int blk = blockIdx.x;
    const float* W; int sblk; int oel;
    if      (blk < 64)  { W = w0; sblk = 0;   oel = 0;      }
    else if (blk < 128) { W = w1; sblk = 64;  oel = 65536;  }
    else if (blk < 320) { W = w2; sblk = 128; oel = 131072; }
    else if (blk < 384) { W = w3; sblk = 320; oel = 327680; }
    else if (blk < 512) { W = w4; sblk = 384; oel = 393216; }
    else                { W = w5; sblk = 512; oel = 524288; }
    int i4 = (blk - sblk) * 256 + threadIdx.x;
    float4 v = ((const float4*)W)[i4];
    ((uint2*)(g_wh + oel))[i4] = make_uint2(pack_f2h(v.x, v.y), pack_f2h(v.z, v.w));
}

// ---------------- utility kernels ------------------
__global__ void zero_f4(float4* p, int n4) {
    int i = blockIdx.x * 256 + threadIdx.x;
    if (i < n4) p[i] = make_float4(0.f, 0.f, 0.f, 0.f);
}

__global__ void scatter_edges(const float* __restrict__ h,
                              const int* __restrict__ src,
                              const int* __restrict__ dst, int E) {
    long gid = (long)blockIdx.x * 256 + threadIdx.x;
    if (gid >= (long)E * H4c) return;
    int e = (int)(gid >> 6);
    int c = (int)(gid & 63);
    int s = __ldg(&src[e]);
    int d = __ldg(&dst[e]);
    float4 v = ((const float4*)h)[(size_t)s * H4c + c];
    float4* p = ((float4*)g_agg) + (size_t)d * H4c + c;
    asm volatile("red.global.add.v4.f32 [%0], {%1,%2,%3,%4};"
                 :: "l"(p), "f"(v.x), "f"(v.y), "f"(v.z), "f"(v.w) : "memory");
}

// scan + inverse index + mask + stats zero, one launch (grid = 128)
__global__ void inv_k(const int* __restrict__ bnn) {
    __shared__ int sm[256];
    int t = threadIdx.x;
    sm[t] = bnn[t];
    __syncthreads();
    for (int off = 1; off < 256; off <<= 1) {
        int v = sm[t] + ((t >= off) ? sm[t - off] : 0);
        __syncthreads();
        sm[t] = v;
        __syncthreads();
    }
    int s = blockIdx.x * 256 + t;
    int b = s >> 7, rr = s & (Mc - 1);
    int cumb = (b == 0) ? 0 : sm[b - 1];
    int nb = sm[b] - cumb;
    bool v = rr < nb;
    g_inv[s] = v ? (cumb + rr) : -1;
    g_mask[s] = v ? 1 : 0;
    if (blockIdx.x == 0) {
        for (int i = t; i < 6 * Hc; i += 256) g_bnstats[i] = 0.f;
    }
}

__device__ __forceinline__ float4 bn4(float4 x, float4 s, float4 q,
                                      float4 g, float4 b, float invN) {
    float4 o;
    { float m = s.x * invN, v = q.x * invN - m * m; o.x = g.x * (x.x - m) * rsqrtf(v + 1e-5f) + b.x; }
    { float m = s.y * invN, v = q.y * invN - m * m; o.y = g.y * (x.y - m) * rsqrtf(v + 1e-5f) + b.y; }
    { float m = s.z * invN, v = q.z * invN - m * m; o.z = g.z * (x.z - m) * rsqrtf(v + 1e-5f) + b.z; }
    { float m = s.w * invN, v = q.w * invN - m * m; o.w = g.w * (x.w - m) * rsqrtf(v + 1e-5f) + b.w; }
    return o;
}

__global__ void bn_combine(const float* __restrict__ PL, const float* __restrict__ PA,
                           const float* __restrict__ gl, const float* __restrict__ bl,
                           const float* __restrict__ ga, const float* __restrict__ ba,
                           const float* __restrict__ stl, const float* __restrict__ sta,
                           float* __restrict__ out, float invN, int n4tot) {
    int gid = blockIdx.x * 256 + threadIdx.x;
    if (gid >= n4tot) return;
    int c4 = gid & 63;
    float4 a = bn4(((const float4*)PL)[gid], ((const float4*)stl)[c4],
                   ((const float4*)stl)[H4c + c4], ((const float4*)gl)[c4],
                   ((const float4*)bl)[c4], invN);
    float4 b = bn4(((const float4*)PA)[gid], ((const float4*)sta)[c4],
                   ((const float4*)sta)[H4c + c4], ((const float4*)ga)[c4],
                   ((const float4*)ba)[c4], invN);
    a.x += b.x; a.y += b.y; a.z += b.z; a.w += b.w;
    ((float4*)out)[gid] = a;
}

__global__ void bn_apply(const float* __restrict__ X, const float* __restrict__ st,
                         const float* __restrict__ gamma, const float* __restrict__ beta,
                         float* __restrict__ out, float invN, int n4total) {
    int gid = blockIdx.x * 256 + threadIdx.x;
    if (gid >= n4total) return;
    int c4 = gid & 63;
    float4 o = bn4(((const float4*)X)[gid], ((const float4*)st)[c4],
                   ((const float4*)st)[H4c + c4], ((const float4*)gamma)[c4],
                   ((const float4*)beta)[c4], invN);
    ((float4*)out)[gid] = o;
}

// ---------------- tensor-core attention -------------
// block = (graph, head), 128 threads / 4 warps.
// scores = (Q*sc2) @ K^T (fp16 hi/lo x fp16, 2 passes), base-2 online softmax,
// P (fp16, reused from C-frags as A-frags) @ V^T (fp16, explicit transpose).
#define AQHI 0
#define AQLO 10240
#define AKS  20480
#define AVT  30720          // 32 rows x 272B
#define AMB  39424
#define ASMEM 39936

__global__ __launch_bounds__(128)
void attn_mma() {
    __shared__ char smem[ASMEM];
    const uint32_t sb = smem_u32(smem);
    const int b = blockIdx.x >> 3;
    const int head = blockIdx.x & 7;
    const int tid = threadIdx.x;
    const int wid = tid >> 5, lane = tid & 31;
    const int wm = wid * 32;

    const float sc2 = 0.17677669529663687f * 1.44269504088896341f;

    // ---- stage Q(hi/lo, scaled), K, V^T, mask bias ----
    {
        const float* base = g_qkv + (size_t)(b * Mc + tid) * (3 * Hc);
        const float* qp = base + head * DHc;
        const float* kp = base + Hc + head * DHc;
        const float* vp = base + 2 * Hc + head * DHc;
#pragma unroll
        for (int j = 0; j < 8; j++) {
            float4 q4 = *(const float4*)(qp + j * 4);
            q4.x *= sc2; q4.y *= sc2; q4.z *= sc2; q4.w *= sc2;
            __half hx = __float2half_rn(q4.x), hy = __float2half_rn(q4.y);
            __half hz = __float2half_rn(q4.z), hw = __float2half_rn(q4.w);
            *(uint2*)(smem + AQHI + tid * ROWB + j * 8) =
                make_uint2(pack_h2(hx, hy), pack_h2(hz, hw));
            *(uint2*)(smem + AQLO + tid * ROWB + j * 8) = make_uint2(
                pack_f2h(q4.x - __half2float(hx), q4.y - __half2float(hy)),
                pack_f2h(q4.z - __half2float(hz), q4.w - __half2float(hw)));
            float4 k4 = *(const float4*)(kp + j * 4);
            *(uint2*)(smem + AKS + tid * ROWB + j * 8) =
                make_uint2(pack_f2h(k4.x, k4.y), pack_f2h(k4.z, k4.w));
            float4 v4 = *(const float4*)(vp + j * 4);
            __half* vt = (__half*)(smem + AVT);
            vt[(j * 4 + 0) * 136 + tid] = __float2half_rn(v4.x);
            vt[(j * 4 + 1) * 136 + tid] = __float2half_rn(v4.y);
            vt[(j * 4 + 2) * 136 + tid] = __float2half_rn(v4.z);
            vt[(j * 4 + 3) * 136 + tid] = __float2half_rn(v4.w);
        }
        ((float*)(smem + AMB))[tid] = g_mask[b * Mc + tid] ? 0.f : -1e30f;
    }
    __syncthreads();

    // ---- QK^T: sc[mt][nt][4] over n=128 ----
    float sc[2][16][4];
#pragma unroll
    for (int mt = 0; mt < 2; mt++)
#pragma unroll
        for (int nt = 0; nt < 16; nt++)
#pragma unroll
            for (int q = 0; q < 4; q++) sc[mt][nt][q] = 0.f;

#pragma unroll
    for (int pass = 0; pass < 2; pass++) {
        const uint32_t aoff = pass ? AQLO : AQHI;
#pragma unroll
        for (int ks = 0; ks < 2; ks++) {
            uint32_t ah[2][4];
#pragma unroll
            for (int mt = 0; mt < 2; mt++) {
                uint32_t arow = wm + mt * 16 + (lane & 15);
                uint32_t kb = ks * 32 + ((lane >> 4) * 16);
                LDSM_X4(ah[mt][0], ah[mt][1], ah[mt][2], ah[mt][3],
                        sb + aoff + arow * ROWB + kb);
            }
#pragma unroll
            for (int np = 0; np < 8; np++) {
                uint32_t nrow = np * 16 + ((lane >> 4) << 3) + (lane & 7);
                uint32_t kb = ks * 32 + (((lane >> 3) & 1) << 4);
                uint32_t bh[4];
                LDSM_X4(bh[0], bh[1], bh[2], bh[3], sb + AKS + nrow * ROWB + kb);
#pragma unroll
                for (int mt = 0; mt < 2; mt++) {
                    MMA16816(sc[mt][2 * np],     ah[mt], bh[0], bh[1]);
                    MMA16816(sc[mt][2 * np + 1], ah[mt], bh[2], bh[3]);
                }
            }
        }
    }

    // ---- mask + softmax (base 2, scores pre-scaled) ----
    const float* mb = (const float*)(smem + AMB);
#pragma unroll
    for (int nt = 0; nt < 16; nt++) {
        float2 mp = *(const float2*)(mb + nt * 8 + (lane & 3) * 2);
#pragma unroll
        for (int mt = 0; mt < 2; mt++) {
            sc[mt][nt][0] += mp.x; sc[mt][nt][1] += mp.y;
            sc[mt][nt][2] += mp.x; sc[mt][nt][3] += mp.y;
        }
    }
    float rinv[4];
#pragma unroll
    for (int rg = 0; rg < 4; rg++) {
        const int mt = rg >> 1, off = (rg & 1) * 2;
        float m = -3.0e38f;
#pragma unroll
        for (int nt = 0; nt < 16; nt++)
            m = fmaxf(m, fmaxf(sc[mt][nt][off], sc[mt][nt][off + 1]));
        m = fmaxf(m, __shfl_xor_sync(0xffffffff, m, 1));
        m = fmaxf(m, __shfl_xor_sync(0xffffffff, m, 2));
        float l = 0.f;
#pragma unroll
        for (int nt = 0; nt < 16; nt++) {
            float p0 = ex2f(sc[mt][nt][off] - m);
            float p1 = ex2f(sc[mt][nt][off + 1] - m);
            sc[mt][nt][off] = p0; sc[mt][nt][off + 1] = p1;
            l += p0 + p1;
        }
        l += __shfl_xor_sync(0xffffffff, l, 1);
        l += __shfl_xor_sync(0xffffffff, l, 2);
        rinv[rg] = 1.f / l;
    }

    // ---- P @ V^T: av[mt][ndt][4] ----
    float av[2][4][4];
#pragma unroll
    for (int mt = 0; mt < 2; mt++)
#pragma unroll
        for (int nd = 0; nd < 4; nd++)
#pragma unroll
            for (int q = 0; q < 4; q++) av[mt][nd][q] = 0.f;

#pragma unroll
    for (int j = 0; j < 8; j++) {
        uint32_t pa[2][4];
#pragma unroll
        for (int mt = 0; mt < 2; mt++) {
            pa[mt][0] = pack_f2h(sc[mt][2 * j][0],     sc[mt][2 * j][1]);
            pa[mt][1] = pack_f2h(sc[mt][2 * j][2],     sc[mt][2 * j][3]);
            pa[mt][2] = pack_f2h(sc[mt][2 * j + 1][0], sc[mt][2 * j + 1][1]);
            pa[mt][3] = pack_f2h(sc[mt][2 * j + 1][2], sc[mt][2 * j + 1][3]);
        }
#pragma unroll
        for (int np = 0; np < 2; np++) {
            uint32_t nrow = np * 16 + ((lane >> 4) << 3) + (lane & 7);
            uint32_t kb = j * 32 + (((lane >> 3) & 1) << 4);
            uint32_t vb[4];
            LDSM_X4(vb[0], vb[1], vb[2], vb[3], sb + AVT + nrow * 272 + kb);
#pragma unroll
            for (int mt = 0; mt < 2; mt++) {
                MMA16816(av[mt][2 * np],     pa[mt], vb[0], vb[1]);
                MMA16816(av[mt][2 * np + 1], pa[mt], vb[2], vb[3]);
            }
        }
    }

    // ---- write normalized output ----
#pragma unroll
    for (int mt = 0; mt < 2; mt++) {
        int row = b * Mc + wm + mt * 16 + (lane >> 2);
#pragma unroll
        for (int nd = 0; nd < 4; nd++) {
            int col = head * DHc + nd * 8 + (lane & 3) * 2;
            float i0 = rinv[mt * 2 + 0], i1 = rinv[mt * 2 + 1];
            *(float2*)(g_adense + (size_t)row * Hc + col) =
                make_float2(av[mt][nd][0] * i0, av[mt][nd][1] * i0);
            *(float2*)(g_adense + (size_t)(row + 8) * Hc + col) =
                make_float2(av[mt][nd][2] * i1, av[mt][nd][3] * i1);
        }
    }
}

// ---------------- host orchestration ----------------
static inline int cdiv(long a, int b) { return (int)((a + b - 1) / b); }

extern "C" void kernel_launch(void* const* d_in, const int* in_sizes, int n_in,
                              void* d_out, int out_size) {
    const float* h         = (const float*)d_in[0];
    const float* gin_w1    = (const float*)d_in[1];
    const float* gin_b1    = (const float*)d_in[2];
    const float* gin_w2    = (const float*)d_in[3];
    const float* gin_b2    = (const float*)d_in[4];
    const float* in_proj_w = (const float*)d_in[5];
    const float* in_proj_b = (const float*)d_in[6];
    const float* out_proj_w= (const float*)d_in[7];
    const float* out_proj_b= (const float*)d_in[8];
    const float* bnl_g     = (const float*)d_in[9];
    const float* bnl_b     = (const float*)d_in[10];
    const float* bna_g     = (const float*)d_in[11];
    const float* bna_b     = (const float*)d_in[12];
    const float* bno_g     = (const float*)d_in[13];
    const float* bno_b     = (const float*)d_in[14];
    const float* ffn1_w    = (const float*)d_in[15];
    const float* ffn1_b    = (const float*)d_in[16];
    const float* ffn2_w    = (const float*)d_in[17];
    const float* ffn2_b    = (const float*)d_in[18];
    const int*   e_src     = (const int*)d_in[19];
    const int*   e_dst     = (const int*)d_in[20];
    const int*   bnn       = (const int*)d_in[21];

    const int nN = in_sizes[0] / Hc;      // 32768
    const int nE = in_sizes[19];          // 524288
    const int n4 = nN * H4c;
    const float invN = 1.0f / (float)nN;

    float *p_agg, *p_z1, *p_PL, *p_PA, *p_PO, *p_qkv, *p_adense, *p_hh, *p_f1, *p_st;
    int *p_inv;
    __half* p_wh;
    cudaGetSymbolAddress((void**)&p_agg,    g_agg);
    cudaGetSymbolAddress((void**)&p_z1,     g_z1);
    cudaGetSymbolAddress((void**)&p_PL,     g_pre);
    cudaGetSymbolAddress((void**)&p_PA,     g_hlocal);
    cudaGetSymbolAddress((void**)&p_PO,     g_hd);
    cudaGetSymbolAddress((void**)&p_qkv,    g_qkv);
    cudaGetSymbolAddress((void**)&p_adense, g_adense);
    cudaGetSymbolAddress((void**)&p_hh,     g_hh);
    cudaGetSymbolAddress((void**)&p_f1,     g_f1);
    cudaGetSymbolAddress((void**)&p_st,     g_bnstats);
    cudaGetSymbolAddress((void**)&p_inv,    g_inv);
    cudaGetSymbolAddress((void**)&p_wh,     g_wh);

    float* st_l = p_st;
    float* st_a = p_st + 2 * Hc;
    float* st_o = p_st + 4 * Hc;

    cudaFuncSetAttribute(mma_gemm<true>,  cudaFuncAttributeMaxDynamicSharedMemorySize, GEMM_SMEM);
    cudaFuncSetAttribute(mma_gemm<false>, cudaFuncAttributeMaxDynamicSharedMemorySize, GEMM_SMEM);

    const int OFF_GIN1 = 0;
    const int OFF_GIN2 = 65536;
    const int OFF_QKV  = 131072;
    const int OFF_OUT  = 327680;
    const int OFF_F1   = 393216;
    const int OFF_F2   = 524288;

    auto gemm = [&](bool relu, const float* A, const float* A2, const int* a_inv,
                    int woff, const float* bias, const float* res, const int* c_inv,
                    float* C, float* stats, int Nc, int K) {
        dim3 grid(Nc / 128, nN / 128);
        if (relu)
            mma_gemm<true><<<grid, 256, GEMM_SMEM>>>(A, A2, a_inv, p_wh + woff,
                                                     bias, res, c_inv, C, stats, Nc, K);
        else
            mma_gemm<false><<<grid, 256, GEMM_SMEM>>>(A, A2, a_inv, p_wh + woff,
                                                      bias, res, c_inv, C, stats, Nc, K);
    };

    // launch 0: weight convert (single launch)
    wsplit_all<<<640, 256>>>(gin_w1, gin_w2, in_proj_w, out_proj_w, ffn1_w, ffn2_w);
    // launch 1: zero agg
    zero_f4<<<cdiv(n4, 256), 256>>>((float4*)p_agg, n4);
    // launch 2: edge scatter
    scatter_edges<<<cdiv((long)nE * H4c, 256), 256>>>(h, e_src, e_dst, nE);
    // launch 3: scan + inverse index + mask + stats zero
    inv_k<<<Bc * Mc / 256, 256>>>(bnn);

    // launch 4-5: GIN (launch 5 = gin2 is the ncu-profiled one)
    gemm(true,  h,    p_agg,   nullptr, OFF_GIN1, gin_b1, nullptr, nullptr, p_z1, nullptr, Hc, Hc);
    gemm(false, p_z1, nullptr, nullptr, OFF_GIN2, gin_b2, h,       nullptr, p_PL, st_l,    Hc, Hc);

    // launch 6-8: attention branch
    gemm(false, h, nullptr, p_inv, OFF_QKV, in_proj_b, nullptr, nullptr, p_qkv, nullptr, 3 * Hc, Hc);
    attn_mma<<<Bc * NHc, 128>>>();
    gemm(false, p_adense, nullptr, nullptr, OFF_OUT, out_proj_b, h, p_inv, p_PA, st_a, Hc, Hc);

    // launch 9: combine both BNs -> hh
    bn_combine<<<cdiv(n4, 256), 256>>>(p_PL, p_PA, bnl_g, bnl_b, bna_g, bna_b,
                                       st_l, st_a, p_hh, invN, n4);

    // launch 10-12: FFN + final norm
    gemm(true,  p_hh, nullptr, nullptr, OFF_F1, ffn1_b, nullptr, nullptr, p_f1, nullptr, 2 * Hc, Hc);
    gemm(false, p_f1, nullptr, nullptr, OFF_F2, ffn2_b, p_hh,    nullptr, p_PO, st_o,    Hc, 2 * Hc);
    bn_apply<<<cdiv(n4, 256), 256>>>(p_PO, st_o, bno_g, bno_b, (float*)d_out, invN, n4);
}

// round 7
// speedup vs baseline: 2.0746x; 1.0271x over previous
#include <cuda_runtime.h>
#include <cuda_bf16.h>
#include <cuda_fp16.h>
#include <cstdint>
#include <cstdio>

// ---------------- problem constants ----------------
#define Hc   256
#define H4c  64
#define Bc   256
#define Mc   128
#define NHc  8
#define DHc  32
#define NMAX 32768

// ---------------- device scratch -------------------
__device__ float g_agg   [NMAX * Hc];
__device__ float g_PL    [NMAX * Hc];
__device__ float g_PA    [NMAX * Hc];
__device__ float g_PO    [NMAX * Hc];
__device__ float g_qkv   [Bc * Mc * 3 * Hc];
__device__ float g_hh    [NMAX * Hc];
__device__ float g_bnstats[3 * 2 * Hc];
__device__ int   g_inv   [Bc * Mc];
__device__ int   g_mask  [Bc * Mc];
#define WTOT 655360
__device__ __align__(16) __half g_wh[WTOT];
// fp16 hi/lo activation buffers
__device__ __align__(16) __half g_h16hi [NMAX * Hc];
__device__ __align__(16) __half g_h16lo [NMAX * Hc];
__device__ __align__(16) __half g_ha16hi[NMAX * Hc];
__device__ __align__(16) __half g_ha16lo[NMAX * Hc];
__device__ __align__(16) __half g_z116hi[NMAX * Hc];
__device__ __align__(16) __half g_z116lo[NMAX * Hc];
__device__ __align__(16) __half g_ad16hi[NMAX * Hc];
__device__ __align__(16) __half g_ad16lo[NMAX * Hc];
__device__ __align__(16) __half g_hh16hi[NMAX * Hc];
__device__ __align__(16) __half g_hh16lo[NMAX * Hc];
__device__ __align__(16) __half g_f116hi[NMAX * 2 * Hc];
__device__ __align__(16) __half g_f116lo[NMAX * 2 * Hc];
__device__ __align__(16) __half g_zrow[64];   // zero row for padded gathers

// ---------------- PTX helpers ----------------------
__device__ __forceinline__ uint32_t smem_u32(const void* p) {
    uint32_t a;
    asm("{ .reg .u64 t; cvta.to.shared.u64 t, %1; cvt.u32.u64 %0, t; }"
        : "=r"(a) : "l"(p));
    return a;
}
#define LDSM_X4(r0, r1, r2, r3, addr)                                    \
    asm volatile("ldmatrix.sync.aligned.m8n8.x4.shared.b16 {%0,%1,%2,%3}, [%4];" \
                 : "=r"(r0), "=r"(r1), "=r"(r2), "=r"(r3) : "r"(addr))
#define MMA16816(d, a, b0, b1)                                           \
    asm volatile("mma.sync.aligned.m16n8k16.row.col.f32.f16.f16.f32 "    \
                 "{%0,%1,%2,%3}, {%4,%5,%6,%7}, {%8,%9}, {%0,%1,%2,%3};" \
                 : "+f"((d)[0]), "+f"((d)[1]), "+f"((d)[2]), "+f"((d)[3]) \
                 : "r"((a)[0]), "r"((a)[1]), "r"((a)[2]), "r"((a)[3]),   \
                   "r"(b0), "r"(b1))
#define CP_ASYNC16(dst, src)                                             \
    asm volatile("cp.async.ca.shared.global [%0], [%1], 16;" :: "r"(dst), "l"(src))
#define CP_COMMIT() asm volatile("cp.async.commit_group;")
#define CP_WAIT0()  asm volatile("cp.async.wait_group 0;" ::: "memory")

__device__ __forceinline__ uint32_t pack_h2(__half a, __half b) {
    __half2 p{a, b};
    return *(uint32_t*)&p;
}
__device__ __forceinline__ uint32_t pack_f2h(float a, float b) {
    return pack_h2(__float2half_rn(a), __float2half_rn(b));
}
__device__ __forceinline__ float ex2f(float x) {
    float y;
    asm("ex2.approx.ftz.f32 %0, %1;" : "=f"(y) : "f"(x));
    return y;
}

// ---------------- pure-tensor fp16 hi/lo GEMM ------
// C = act(A @ W^T + bias [+res]); A pre-split fp16 hi/lo buffers, W fp16.
// Outputs any of: C32 (fp32), Chi/Clo (fp16 hi/lo), stats; optional row
// gather (a_inv) and scatter-with-residual (c_inv).
#define ROWB 80
#define OFF_AHI 0
#define OFF_ALO 10240
#define OFF_B   20480
#define BUFSZ   30720
#define GEMM_SMEM (2 * BUFSZ)

template<bool RELU>
__global__ __launch_bounds__(256, 2)
void mma_gemm(const __half* __restrict__ Ahi, const __half* __restrict__ Alo,
              const int* __restrict__ a_inv, const __half* __restrict__ W,
              const float* __restrict__ bias, const float* __restrict__ res,
              const int* __restrict__ c_inv, float* __restrict__ C32,
              __half* __restrict__ Chi, __half* __restrict__ Clo,
              float* __restrict__ stats, int Nc, int K) {
    extern __shared__ char smem[];
    const uint32_t sb = smem_u32(smem);
    const int tid = threadIdx.x;
    const int wid = tid >> 5, lane = tid & 31;
    const int wm = (wid >> 1) * 32, wn = (wid & 1) * 64;
    const int row0 = blockIdx.y * 128;
    const int col0 = blockIdx.x * 128;
    const int r = tid >> 1, half = tid & 1;

    const __half *pAhi, *pAlo;
    bool avalid = true;
    {
        int arow = row0 + r;
        if (a_inv) {
            int nd = a_inv[arow];
            avalid = nd >= 0;
            int nn = avalid ? nd : 0;
            pAhi = Ahi + (size_t)nn * K;
            pAlo = Alo + (size_t)nn * K;
        } else {
            pAhi = Ahi + (size_t)arow * K;
            pAlo = Alo + (size_t)arow * K;
        }
    }

    float acc[2][8][4];
#pragma unroll
    for (int mt = 0; mt < 2; mt++)
#pragma unroll
        for (int nt = 0; nt < 8; nt++)
#pragma unroll
            for (int q = 0; q < 4; q++) acc[mt][nt][q] = 0.f;

    const int nit = K >> 5;

    auto issue = [&](int i) {
        const uint32_t bo = (uint32_t)(i & 1) * BUFSZ;
        const int k0 = i * 32;
        const char* sAh = avalid ? (const char*)(pAhi + k0 + half * 16)
                                 : (const char*)(g_zrow + half * 16);
        const char* sAl = avalid ? (const char*)(pAlo + k0 + half * 16)
                                 : (const char*)(g_zrow + half * 16);
        uint32_t dA = sb + bo + OFF_AHI + r * ROWB + half * 32;
        CP_ASYNC16(dA, sAh); CP_ASYNC16(dA + 16, sAh + 16);
        uint32_t dL = sb + bo + OFF_ALO + r * ROWB + half * 32;
        CP_ASYNC16(dL, sAl); CP_ASYNC16(dL + 16, sAl + 16);
        const char* gb = (const char*)(W + (size_t)(col0 + r) * K + k0 + half * 16);
        uint32_t dB = sb + bo + OFF_B + r * ROWB + half * 32;
        CP_ASYNC16(dB, gb); CP_ASYNC16(dB + 16, gb + 16);
        CP_COMMIT();
    };

    issue(0);
    for (int i = 0; i < nit; i++) {
        const uint32_t boff = (uint32_t)(i & 1) * BUFSZ;
        CP_WAIT0();
        __syncthreads();
        if (i + 1 < nit) issue(i + 1);
#pragma unroll
        for (int ks = 0; ks < 2; ks++) {
            uint32_t ah[2][4], al[2][4];
#pragma unroll
            for (int mt = 0; mt < 2; mt++) {
                uint32_t arow = wm + mt * 16 + (lane & 15);
                uint32_t kb = ks * 32 + ((lane >> 4) * 16);
                uint32_t ad = sb + boff + OFF_AHI + arow * ROWB + kb;
                LDSM_X4(ah[mt][0], ah[mt][1], ah[mt][2], ah[mt][3], ad);
                LDSM_X4(al[mt][0], al[mt][1], al[mt][2], al[mt][3],
                        ad + (OFF_ALO - OFF_AHI));
            }
#pragma unroll
            for (int np = 0; np < 4; np++) {
                uint32_t nrow = wn + np * 16 + ((lane >> 4) << 3) + (lane & 7);
                uint32_t kb = ks * 32 + (((lane >> 3) & 1) << 4);
                uint32_t bd = sb + boff + OFF_B + nrow * ROWB + kb;
                uint32_t bh[4];
                LDSM_X4(bh[0], bh[1], bh[2], bh[3], bd);
#pragma unroll
                for (int mt = 0; mt < 2; mt++) {
                    MMA16816(acc[mt][2 * np],     ah[mt], bh[0], bh[1]);
                    MMA16816(acc[mt][2 * np],     al[mt], bh[0], bh[1]);
                    MMA16816(acc[mt][2 * np + 1], ah[mt], bh[2], bh[3]);
                    MMA16816(acc[mt][2 * np + 1], al[mt], bh[2], bh[3]);
                }
            }
        }
        __syncthreads();
    }

    // ---- epilogue ----
    float* ssum = (float*)smem;
    float* ssq  = ssum + 128;
    if (stats) {
        if (tid < 128) { ssum[tid] = 0.f; ssq[tid] = 0.f; }
        __syncthreads();
    }
    int rA0 = row0 + wm + (lane >> 2);
    int nmap[2][2];
    if (c_inv) {
        nmap[0][0] = c_inv[rA0];      nmap[0][1] = c_inv[rA0 + 8];
        nmap[1][0] = c_inv[rA0 + 16]; nmap[1][1] = c_inv[rA0 + 24];
    }
#pragma unroll
    for (int nt = 0; nt < 8; nt++) {
        int c = col0 + wn + nt * 8 + (lane & 3) * 2;
        float2 bi = *(const float2*)(bias + c);
        float cs0 = 0.f, cs1 = 0.f, cq0 = 0.f, cq1 = 0.f;
#pragma unroll
        for (int mt = 0; mt < 2; mt++) {
            int ra = rA0 + mt * 16;
            float o0 = acc[mt][nt][0] + bi.x, o1 = acc[mt][nt][1] + bi.y;
            float o2 = acc[mt][nt][2] + bi.x, o3 = acc[mt][nt][3] + bi.y;
            if (c_inv) {
                int na = nmap[mt][0], nb = nmap[mt][1];
                if (na >= 0) {
                    float2 rv = *(const float2*)(res + (size_t)na * Nc + c);
                    o0 += rv.x; o1 += rv.y;
                    *(float2*)(C32 + (size_t)na * Nc + c) = make_float2(o0, o1);
                    cs0 += o0; cq0 += o0 * o0; cs1 += o1; cq1 += o1 * o1;
                }
                if (nb >= 0) {
                    float2 rv = *(const float2*)(res + (size_t)nb * Nc + c);
                    o2 += rv.x; o3 += rv.y;
                    *(float2*)(C32 + (size_t)nb * Nc + c) = make_float2(o2, o3);
                    cs0 += o2; cq0 += o2 * o2; cs1 += o3; cq1 += o3 * o3;
                }
            } else {
                if (res) {
                    float2 r0 = *(const float2*)(res + (size_t)ra * Nc + c);
                    float2 r1 = *(const float2*)(res + (size_t)(ra + 8) * Nc + c);
                    o0 += r0.x; o1 += r0.y; o2 += r1.x; o3 += r1.y;
                }
                if (RELU) {
                    o0 = fmaxf(o0, 0.f); o1 = fmaxf(o1, 0.f);
                    o2 = fmaxf(o2, 0.f); o3 = fmaxf(o3, 0.f);
                }
                if (C32) {
                    *(float2*)(C32 + (size_t)ra * Nc + c) = make_float2(o0, o1);
                    *(float2*)(C32 + (size_t)(ra + 8) * Nc + c) = make_float2(o2, o3);
                }
                if (Chi) {
                    __half h0 = __float2half_rn(o0), h1 = __float2half_rn(o1);
                    __half h2 = __float2half_rn(o2), h3 = __float2half_rn(o3);
                    *(uint32_t*)(Chi + (size_t)ra * Nc + c) = pack_h2(h0, h1);
                    *(uint32_t*)(Clo + (size_t)ra * Nc + c) =
                        pack_f2h(o0 - __half2float(h0), o1 - __half2float(h1));
                    *(uint32_t*)(Chi + (size_t)(ra + 8) * Nc + c) = pack_h2(h2, h3);
                    *(uint32_t*)(Clo + (size_t)(ra + 8) * Nc + c) =
                        pack_f2h(o2 - __half2float(h2), o3 - __half2float(h3));
                }
                if (stats) {
                    cs0 += o0 + o2; cq0 += o0 * o0 + o2 * o2;
                    cs1 += o1 + o3; cq1 += o1 * o1 + o3 * o3;
                }
            }
        }
        if (stats) {
            int lc = c - col0;
            atomicAdd(&ssum[lc], cs0); atomicAdd(&ssq[lc], cq0);
            atomicAdd(&ssum[lc + 1], cs1); atomicAdd(&ssq[lc + 1], cq1);
        }
    }
    if (stats) {
        __syncthreads();
        if (tid < 128) {
            atomicAdd(&stats[col0 + tid], ssum[tid]);
            atomicAdd(&stats[Hc + col0 + tid], ssq[tid]);
        }
    }
}

// ---------------- single-launch weight convert ------
__global__ void wsplit_all(const float* w0, const float* w1, const float* w2,
                           const float* w3, const float* w4, const float* w5) {
    int blk = blockIdx.x;
    const float* W; int sblk; int oel;
    if      (blk < 64)  { W = w0; sblk = 0;   oel = 0;      }
    else if (blk < 128) { W = w1; sblk = 64;  oel = 65536;  }
    else if (blk < 320) { W = w2; sblk = 128; oel = 131072; }
    else if (blk < 384) { W = w3; sblk = 320; oel = 327680; }
    else if (blk < 512) { W = w4; sblk = 384; oel = 393216; }
    else                { W = w5; sblk = 512; oel = 524288; }
    int i4 = (blk - sblk) * 256 + threadIdx.x;
    float4 v = ((const float4*)W)[i4];
    ((uint2*)(g_wh + oel))[i4] = make_uint2(pack_f2h(v.x, v.y), pack_f2h(v.z, v.w));
}

// ---------------- utility kernels ------------------
__global__ void zero_f4(float4* p, int n4) {
    int i = blockIdx.x * 256 + threadIdx.x;
    if (i < n4) p[i] = make_float4(0.f, 0.f, 0.f, 0.f);
}

__global__ void scatter_edges(const float* __restrict__ h,
                              const int* __restrict__ src,
                              const int* __restrict__ dst, int E) {
    long gid = (long)blockIdx.x * 256 + threadIdx.x;
    if (gid >= (long)E * H4c) return;
    int e = (int)(gid >> 6);
    int c = (int)(gid & 63);
    int s = __ldg(&src[e]);
    int d = __ldg(&dst[e]);
    float4 v = ((const float4*)h)[(size_t)s * H4c + c];
    float4* p = ((float4*)g_agg) + (size_t)d * H4c + c;
    asm volatile("red.global.add.v4.f32 [%0], {%1,%2,%3,%4};"
                 :: "l"(p), "f"(v.x), "f"(v.y), "f"(v.z), "f"(v.w) : "memory");
}

// scan + inverse index + mask + stats zero
__global__ void inv_k(const int* __restrict__ bnn) {
    __shared__ int sm[256];
    int t = threadIdx.x;
    sm[t] = bnn[t];
    __syncthreads();
    for (int off = 1; off < 256; off <<= 1) {
        int v = sm[t] + ((t >= off) ? sm[t - off] : 0);
        __syncthreads();
        sm[t] = v;
        __syncthreads();
    }
    int s = blockIdx.x * 256 + t;
    int b = s >> 7, rr = s & (Mc - 1);
    int cumb = (b == 0) ? 0 : sm[b - 1];
    int nb = sm[b] - cumb;
    bool v = rr < nb;
    g_inv[s] = v ? (cumb + rr) : -1;
    g_mask[s] = v ? 1 : 0;
    if (blockIdx.x == 0) {
        for (int i = t; i < 6 * Hc; i += 256) g_bnstats[i] = 0.f;
    }
}

// h, h+agg -> fp16 hi/lo buffers (one pass after scatter)
__global__ void prep_convert(const float* __restrict__ h, int n4) {
    int gid = blockIdx.x * 256 + threadIdx.x;
    if (gid >= n4) return;
    float4 hv = ((const float4*)h)[gid];
    float4 av = ((const float4*)g_agg)[gid];
    __half a0 = __float2half_rn(hv.x), a1 = __float2half_rn(hv.y);
    __half a2 = __float2half_rn(hv.z), a3 = __float2half_rn(hv.w);
    ((uint2*)g_h16hi)[gid] = make_uint2(pack_h2(a0, a1), pack_h2(a2, a3));
    ((uint2*)g_h16lo)[gid] = make_uint2(
        pack_f2h(hv.x - __half2float(a0), hv.y - __half2float(a1)),
        pack_f2h(hv.z - __half2float(a2), hv.w - __half2float(a3)));
    float sx = hv.x + av.x, sy = hv.y + av.y, sz = hv.z + av.z, sw = hv.w + av.w;
    __half b0 = __float2half_rn(sx), b1 = __float2half_rn(sy);
    __half b2 = __float2half_rn(sz), b3 = __float2half_rn(sw);
    ((uint2*)g_ha16hi)[gid] = make_uint2(pack_h2(b0, b1), pack_h2(b2, b3));
    ((uint2*)g_ha16lo)[gid] = make_uint2(
        pack_f2h(sx - __half2float(b0), sy - __half2float(b1)),
        pack_f2h(sz - __half2float(b2), sw - __half2float(b3)));
}

__device__ __forceinline__ float4 bn4(float4 x, float4 s, float4 q,
                                      float4 g, float4 b, float invN) {
    float4 o;
    { float m = s.x * invN, v = q.x * invN - m * m; o.x = g.x * (x.x - m) * rsqrtf(v + 1e-5f) + b.x; }
    { float m = s.y * invN, v = q.y * invN - m * m; o.y = g.y * (x.y - m) * rsqrtf(v + 1e-5f) + b.y; }
    { float m = s.z * invN, v = q.z * invN - m * m; o.z = g.z * (x.z - m) * rsqrtf(v + 1e-5f) + b.z; }
    { float m = s.w * invN, v = q.w * invN - m * m; o.w = g.w * (x.w - m) * rsqrtf(v + 1e-5f) + b.w; }
    return o;
}

// hh = bn_local(PL) + bn_attn(PA); writes fp32 + fp16 hi/lo
__global__ void bn_combine(const float* __restrict__ PL, const float* __restrict__ PA,
                           const float* __restrict__ gl, const float* __restrict__ bl,
                           const float* __restrict__ ga, const float* __restrict__ ba,
                           const float* __restrict__ stl, const float* __restrict__ sta,
                           float* __restrict__ out, float invN, int n4tot) {
    int gid = blockIdx.x * 256 + threadIdx.x;
    if (gid >= n4tot) return;
    int c4 = gid & 63;
    float4 a = bn4(((const float4*)PL)[gid], ((const float4*)stl)[c4],
                   ((const float4*)stl)[H4c + c4], ((const float4*)gl)[c4],
                   ((const float4*)bl)[c4], invN);
    float4 b = bn4(((const float4*)PA)[gid], ((const float4*)sta)[c4],
                   ((const float4*)sta)[H4c + c4], ((const float4*)ga)[c4],
                   ((const float4*)ba)[c4], invN);
    a.x += b.x; a.y += b.y; a.z += b.z; a.w += b.w;
    ((float4*)out)[gid] = a;
    __half h0 = __float2half_rn(a.x), h1 = __float2half_rn(a.y);
    __half h2 = __float2half_rn(a.z), h3 = __float2half_rn(a.w);
    ((uint2*)g_hh16hi)[gid] = make_uint2(pack_h2(h0, h1), pack_h2(h2, h3));
    ((uint2*)g_hh16lo)[gid] = make_uint2(
        pack_f2h(a.x - __half2float(h0), a.y - __half2float(h1)),
        pack_f2h(a.z - __half2float(h2), a.w - __half2float(h3)));
}

__global__ void bn_apply(const float* __restrict__ X, const float* __restrict__ st,
                         const float* __restrict__ gamma, const float* __restrict__ beta,
                         float* __restrict__ out, float invN, int n4total) {
    int gid = blockIdx.x * 256 + threadIdx.x;
    if (gid >= n4total) return;
    int c4 = gid & 63;
    float4 o = bn4(((const float4*)X)[gid], ((const float4*)st)[c4],
                   ((const float4*)st)[H4c + c4], ((const float4*)gamma)[c4],
                   ((const float4*)beta)[c4], invN);
    ((float4*)out)[gid] = o;
}

// ---------------- tensor-core attention -------------
#define AQHI 0
#define AQLO 10240
#define AKS  20480
#define AVT  30720
#define AMB  39424
#define ASMEM 39936

__global__ __launch_bounds__(128)
void attn_mma() {
    __shared__ char smem[ASMEM];
    const uint32_t sb = smem_u32(smem);
    const int b = blockIdx.x >> 3;
    const int head = blockIdx.x & 7;
    const int tid = threadIdx.x;
    const int wid = tid >> 5, lane = tid & 31;
    const int wm = wid * 32;

    const float sc2 = 0.17677669529663687f * 1.44269504088896341f;

    {
        const float* base = g_qkv + (size_t)(b * Mc + tid) * (3 * Hc);
        const float* qp = base + head * DHc;
        const float* kp = base + Hc + head * DHc;
        const float* vp = base + 2 * Hc + head * DHc;
#pragma unroll
        for (int j = 0; j < 8; j++) {
            float4 q4 = *(const float4*)(qp + j * 4);
            q4.x *= sc2; q4.y *= sc2; q4.z *= sc2; q4.w *= sc2;
            __half hx = __float2half_rn(q4.x), hy = __float2half_rn(q4.y);
            __half hz = __float2half_rn(q4.z), hw = __float2half_rn(q4.w);
            *(uint2*)(smem + AQHI + tid * ROWB + j * 8) =
                make_uint2(pack_h2(hx, hy), pack_h2(hz, hw));
            *(uint2*)(smem + AQLO + tid * ROWB + j * 8) = make_uint2(
                pack_f2h(q4.x - __half2float(hx), q4.y - __half2float(hy)),
                pack_f2h(q4.z - __half2float(hz), q4.w - __half2float(hw)));
            float4 k4 = *(const float4*)(kp + j * 4);
            *(uint2*)(smem + AKS + tid * ROWB + j * 8) =
                make_uint2(pack_f2h(k4.x, k4.y), pack_f2h(k4.z, k4.w));
            float4 v4 = *(const float4*)(vp + j * 4);
            __half* vt = (__half*)(smem + AVT);
            vt[(j * 4 + 0) * 136 + tid] = __float2half_rn(v4.x);
            vt[(j * 4 + 1) * 136 + tid] = __float2half_rn(v4.y);
            vt[(j * 4 + 2) * 136 + tid] = __float2half_rn(v4.z);
            vt[(j * 4 + 3) * 136 + tid] = __float2half_rn(v4.w);
        }
        ((float*)(smem + AMB))[tid] = g_mask[b * Mc + tid] ? 0.f : -1e30f;
    }
    __syncthreads();

    float sc[2][16][4];
#pragma unroll
    for (int mt = 0; mt < 2; mt++)
#pragma unroll
        for (int nt = 0; nt < 16; nt++)
#pragma unroll
            for (int q = 0; q < 4; q++) sc[mt][nt][q] = 0.f;

#pragma unroll
    for (int pass = 0; pass < 2; pass++) {
        const uint32_t aoff = pass ? AQLO : AQHI;
#pragma unroll
        for (int ks = 0; ks < 2; ks++) {
            uint32_t ah[2][4];
#pragma unroll
            for (int mt = 0; mt < 2; mt++) {
                uint32_t arow = wm + mt * 16 + (lane & 15);
                uint32_t kb = ks * 32 + ((lane >> 4) * 16);
                LDSM_X4(ah[mt][0], ah[mt][1], ah[mt][2], ah[mt][3],
                        sb + aoff + arow * ROWB + kb);
            }
#pragma unroll
            for (int np = 0; np < 8; np++) {
                uint32_t nrow = np * 16 + ((lane >> 4) << 3) + (lane & 7);
                uint32_t kb = ks * 32 + (((lane >> 3) & 1) << 4);
                uint32_t bh[4];
                LDSM_X4(bh[0], bh[1], bh[2], bh[3], sb + AKS + nrow * ROWB + kb);
#pragma unroll
                for (int mt = 0; mt < 2; mt++) {
                    MMA16816(sc[mt][2 * np],     ah[mt], bh[0], bh[1]);
                    MMA16816(sc[mt][2 * np + 1], ah[mt], bh[2], bh[3]);
                }
            }
        }
    }

    const float* mb = (const float*)(smem + AMB);
#pragma unroll
    for (int nt = 0; nt < 16; nt++) {
        float2 mp = *(const float2*)(mb + nt * 8 + (lane & 3) * 2);
#pragma unroll
        for (int mt = 0; mt < 2; mt++) {
            sc[mt][nt][0] += mp.x; sc[mt][nt][1] += mp.y;
            sc[mt][nt][2] += mp.x; sc[mt][nt][3] += mp.y;
        }
    }
    float rinv[4];
#pragma unroll
    for (int rg = 0; rg < 4; rg++) {
        const int mt = rg >> 1, off = (rg & 1) * 2;
        float m = -3.0e38f;
#pragma unroll
        for (int nt = 0; nt < 16; nt++)
            m = fmaxf(m, fmaxf(sc[mt][nt][off], sc[mt][nt][off + 1]));
        m = fmaxf(m, __shfl_xor_sync(0xffffffff, m, 1));
        m = fmaxf(m, __shfl_xor_sync(0xffffffff, m, 2));
        float l = 0.f;
#pragma unroll
        for (int nt = 0; nt < 16; nt++) {
            float p0 = ex2f(sc[mt][nt][off] - m);
            float p1 = ex2f(sc[mt][nt][off + 1] - m);
            sc[mt][nt][off] = p0; sc[mt][nt][off + 1] = p1;
            l += p0 + p1;
        }
        l += __shfl_xor_sync(0xffffffff, l, 1);
        l += __shfl_xor_sync(0xffffffff, l, 2);
        rinv[rg] = 1.f / l;
    }

    float av[2][4][4];
#pragma unroll
    for (int mt = 0; mt < 2; mt++)
#pragma unroll
        for (int nd = 0; nd < 4; nd++)
#pragma unroll
            for (int q = 0; q < 4; q++) av[mt][nd][q] = 0.f;

#pragma unroll
    for (int j = 0; j < 8; j++) {
        uint32_t pa[2][4];
#pragma unroll
        for (int mt = 0; mt < 2; mt++) {
            pa[mt][0] = pack_f2h(sc[mt][2 * j][0],     sc[mt][2 * j][1]);
            pa[mt][1] = pack_f2h(sc[mt][2 * j][2],     sc[mt][2 * j][3]);
            pa[mt][2] = pack_f2h(sc[mt][2 * j + 1][0], sc[mt][2 * j + 1][1]);
            pa[mt][3] = pack_f2h(sc[mt][2 * j + 1][2], sc[mt][2 * j + 1][3]);
        }
#pragma unroll
        for (int np = 0; np < 2; np++) {
            uint32_t nrow = np * 16 + ((lane >> 4) << 3) + (lane & 7);
            uint32_t kb = j * 32 + (((lane >> 3) & 1) << 4);
            uint32_t vb[4];
            LDSM_X4(vb[0], vb[1], vb[2], vb[3], sb + AVT + nrow * 272 + kb);
#pragma unroll
            for (int mt = 0; mt < 2; mt++) {
                MMA16816(av[mt][2 * np],     pa[mt], vb[0], vb[1]);
                MMA16816(av[mt][2 * np + 1], pa[mt], vb[2], vb[3]);
            }
        }
    }

    // write output as fp16 hi/lo (feeds out_proj GEMM directly)
#pragma unroll
    for (int mt = 0; mt < 2; mt++) {
        int row = b * Mc + wm + mt * 16 + (lane >> 2);
#pragma unroll
        for (int nd = 0; nd < 4; nd++) {
            int col = head * DHc + nd * 8 + (lane & 3) * 2;
            float i0 = rinv[mt * 2 + 0], i1 = rinv[mt * 2 + 1];
            float x0 = av[mt][nd][0] * i0, x1 = av[mt][nd][1] * i0;
            float x2 = av[mt][nd][2] * i1, x3 = av[mt][nd][3] * i1;
            __half h0 = __float2half_rn(x0), h1 = __float2half_rn(x1);
            __half h2 = __float2half_rn(x2), h3 = __float2half_rn(x3);
            *(uint32_t*)(g_ad16hi + (size_t)row * Hc + col) = pack_h2(h0, h1);
            *(uint32_t*)(g_ad16lo + (size_t)row * Hc + col) =
                pack_f2h(x0 - __half2float(h0), x1 - __half2float(h1));
            *(uint32_t*)(g_ad16hi + (size_t)(row + 8) * Hc + col) = pack_h2(h2, h3);
            *(uint32_t*)(g_ad16lo + (size_t)(row + 8) * Hc + col) =
                pack_f2h(x2 - __half2float(h2), x3 - __half2float(h3));
        }
    }
}

// ---------------- host orchestration ----------------
static inline int cdiv(long a, int b) { return (int)((a + b - 1) / b); }

extern "C" void kernel_launch(void* const* d_in, const int* in_sizes, int n_in,
                              void* d_out, int out_size) {
    const float* h         = (const float*)d_in[0];
    const float* gin_w1    = (const float*)d_in[1];
    const float* gin_b1    = (const float*)d_in[2];
    const float* gin_w2    = (const float*)d_in[3];
    const float* gin_b2    = (const float*)d_in[4];
    const float* in_proj_w = (const float*)d_in[5];
    const float* in_proj_b = (const float*)d_in[6];
    const float* out_proj_w= (const float*)d_in[7];
    const float* out_proj_b= (const float*)d_in[8];
    const float* bnl_g     = (const float*)d_in[9];
    const float* bnl_b     = (const float*)d_in[10];
    const float* bna_g     = (const float*)d_in[11];
    const float* bna_b     = (const float*)d_in[12];
    const float* bno_g     = (const float*)d_in[13];
    const float* bno_b     = (const float*)d_in[14];
    const float* ffn1_w    = (const float*)d_in[15];
    const float* ffn1_b    = (const float*)d_in[16];
    const float* ffn2_w    = (const float*)d_in[17];
    const float* ffn2_b    = (const float*)d_in[18];
    const int*   e_src     = (const int*)d_in[19];
    const int*   e_dst     = (const int*)d_in[20];
    const int*   bnn       = (const int*)d_in[21];

    const int nN = in_sizes[0] / Hc;
    const int nE = in_sizes[19];
    const int n4 = nN * H4c;
    const float invN = 1.0f / (float)nN;

    float *p_agg, *p_PL, *p_PA, *p_PO, *p_qkv, *p_hh, *p_st;
    int *p_inv;
    __half *p_wh, *p_hhi, *p_hlo, *p_hahi, *p_halo, *p_z1hi, *p_z1lo,
           *p_adhi, *p_adlo, *p_hhhi, *p_hhlo, *p_f1hi, *p_f1lo;
    cudaGetSymbolAddress((void**)&p_agg,  g_agg);
    cudaGetSymbolAddress((void**)&p_PL,   g_PL);
    cudaGetSymbolAddress((void**)&p_PA,   g_PA);
    cudaGetSymbolAddress((void**)&p_PO,   g_PO);
    cudaGetSymbolAddress((void**)&p_qkv,  g_qkv);
    cudaGetSymbolAddress((void**)&p_hh,   g_hh);
    cudaGetSymbolAddress((void**)&p_st,   g_bnstats);
    cudaGetSymbolAddress((void**)&p_inv,  g_inv);
    cudaGetSymbolAddress((void**)&p_wh,   g_wh);
    cudaGetSymbolAddress((void**)&p_hhi,  g_h16hi);
    cudaGetSymbolAddress((void**)&p_hlo,  g_h16lo);
    cudaGetSymbolAddress((void**)&p_hahi, g_ha16hi);
    cudaGetSymbolAddress((void**)&p_halo, g_ha16lo);
    cudaGetSymbolAddress((void**)&p_z1hi, g_z116hi);
    cudaGetSymbolAddress((void**)&p_z1lo, g_z116lo);
    cudaGetSymbolAddress((void**)&p_adhi, g_ad16hi);
    cudaGetSymbolAddress((void**)&p_adlo, g_ad16lo);
    cudaGetSymbolAddress((void**)&p_hhhi, g_hh16hi);
    cudaGetSymbolAddress((void**)&p_hhlo, g_hh16lo);
    cudaGetSymbolAddress((void**)&p_f1hi, g_f116hi);
    cudaGetSymbolAddress((void**)&p_f1lo, g_f116lo);

    float* st_l = p_st;
    float* st_a = p_st + 2 * Hc;
    float* st_o = p_st + 4 * Hc;

    cudaFuncSetAttribute(mma_gemm<true>,  cudaFuncAttributeMaxDynamicSharedMemorySize, GEMM_SMEM);
    cudaFuncSetAttribute(mma_gemm<false>, cudaFuncAttributeMaxDynamicSharedMemorySize, GEMM_SMEM);

    const int OFF_GIN1 = 0;
    const int OFF_GIN2 = 65536;
    const int OFF_QKV  = 131072;
    const int OFF_OUT  = 327680;
    const int OFF_F1   = 393216;
    const int OFF_F2   = 524288;

    auto gemm = [&](bool relu, const __half* Ahi, const __half* Alo,
                    const int* a_inv, int woff, const float* bias,
                    const float* res, const int* c_inv, float* C32,
                    __half* Chi, __half* Clo, float* stats, int Nc, int K) {
        dim3 grid(Nc / 128, nN / 128);
        if (relu)
            mma_gemm<true><<<grid, 256, GEMM_SMEM>>>(Ahi, Alo, a_inv, p_wh + woff,
                bias, res, c_inv, C32, Chi, Clo, stats, Nc, K);
        else
            mma_gemm<false><<<grid, 256, GEMM_SMEM>>>(Ahi, Alo, a_inv, p_wh + woff,
                bias, res, c_inv, C32, Chi, Clo, stats, Nc, K);
    };

    wsplit_all<<<640, 256>>>(gin_w1, gin_w2, in_proj_w, out_proj_w, ffn1_w, ffn2_w);
    zero_f4<<<cdiv(n4, 256), 256>>>((float4*)p_agg, n4);
    scatter_edges<<<cdiv((long)nE * H4c, 256), 256>>>(h, e_src, e_dst, nE);
    inv_k<<<Bc * Mc / 256, 256>>>(bnn);
    prep_convert<<<cdiv(n4, 256), 256>>>(h, n4);

    // GIN branch
    gemm(true,  p_hahi, p_halo, nullptr, OFF_GIN1, gin_b1, nullptr, nullptr,
         nullptr, p_z1hi, p_z1lo, nullptr, Hc, Hc);
    gemm(false, p_z1hi, p_z1lo, nullptr, OFF_GIN2, gin_b2, h, nullptr,
         p_PL, nullptr, nullptr, st_l, Hc, Hc);

    // attention branch
    gemm(false, p_hhi, p_hlo, p_inv, OFF_QKV, in_proj_b, nullptr, nullptr,
         p_qkv, nullptr, nullptr, nullptr, 3 * Hc, Hc);
    attn_mma<<<Bc * NHc, 128>>>();
    gemm(false, p_adhi, p_adlo, nullptr, OFF_OUT, out_proj_b, h, p_inv,
         p_PA, nullptr, nullptr, st_a, Hc, Hc);

    // combine BNs
    bn_combine<<<cdiv(n4, 256), 256>>>(p_PL, p_PA, bnl_g, bnl_b, bna_g, bna_b,
                                       st_l, st_a, p_hh, invN, n4);

    // FFN + final norm
    gemm(true,  p_hhhi, p_hhlo, nullptr, OFF_F1, ffn1_b, nullptr, nullptr,
         nullptr, p_f1hi, p_f1lo, nullptr, 2 * Hc, Hc);
    gemm(false, p_f1hi, p_f1lo, nullptr, OFF_F2, ffn2_b, p_hh, nullptr,
         p_PO, nullptr, nullptr, st_o, Hc, 2 * Hc);
    bn_apply<<<cdiv(n4, 256), 256>>>(p_PO, st_o, bno_g, bno_b, (float*)d_out, invN, n4);
}

// round 8
// speedup vs baseline: 2.1338x; 1.0285x over previous
#include <cuda_runtime.h>
#include <cuda_bf16.h>
#include <cuda_fp16.h>
#include <cstdint>
#include <cstdio>

// ---------------- problem constants ----------------
#define Hc   256
#define H4c  64
#define Bc   256
#define Mc   128
#define NHc  8
#define DHc  32
#define NMAX 32768
#define EMAX 524288

// ---------------- device scratch -------------------
__device__ float g_PL    [NMAX * Hc];
__device__ float g_PA    [NMAX * Hc];
__device__ float g_PO    [NMAX * Hc];
__device__ float g_qkv   [Bc * Mc * 3 * Hc];
__device__ float g_hh    [NMAX * Hc];
__device__ float g_bnstats[3 * 2 * Hc];
__device__ int   g_inv   [Bc * Mc];
__device__ int   g_mask  [Bc * Mc];
// CSR by destination
__device__ int   g_deg   [NMAX];
__device__ int   g_cs    [NMAX + 1];
__device__ int   g_cur   [NMAX];
__device__ int   g_csrc  [EMAX];
#define WTOT 655360
__device__ __align__(16) __half g_wh[WTOT];
// fp16 hi/lo activation buffers
__device__ __align__(16) __half g_h16hi [NMAX * Hc];
__device__ __align__(16) __half g_h16lo [NMAX * Hc];
__device__ __align__(16) __half g_ha16hi[NMAX * Hc];
__device__ __align__(16) __half g_ha16lo[NMAX * Hc];
__device__ __align__(16) __half g_z116hi[NMAX * Hc];
__device__ __align__(16) __half g_z116lo[NMAX * Hc];
__device__ __align__(16) __half g_ad16hi[NMAX * Hc];
__device__ __align__(16) __half g_ad16lo[NMAX * Hc];
__device__ __align__(16) __half g_hh16hi[NMAX * Hc];
__device__ __align__(16) __half g_hh16lo[NMAX * Hc];
__device__ __align__(16) __half g_f116hi[NMAX * 2 * Hc];
__device__ __align__(16) __half g_f116lo[NMAX * 2 * Hc];
__device__ __align__(16) __half g_zrow[64];

// ---------------- PTX helpers ----------------------
__device__ __forceinline__ uint32_t smem_u32(const void* p) {
    uint32_t a;
    asm("{ .reg .u64 t; cvta.to.shared.u64 t, %1; cvt.u32.u64 %0, t; }"
        : "=r"(a) : "l"(p));
    return a;
}
#define LDSM_X4(r0, r1, r2, r3, addr)                                    \
    asm volatile("ldmatrix.sync.aligned.m8n8.x4.shared.b16 {%0,%1,%2,%3}, [%4];" \
                 : "=r"(r0), "=r"(r1), "=r"(r2), "=r"(r3) : "r"(addr))
#define MMA16816(d, a, b0, b1)                                           \
    asm volatile("mma.sync.aligned.m16n8k16.row.col.f32.f16.f16.f32 "    \
                 "{%0,%1,%2,%3}, {%4,%5,%6,%7}, {%8,%9}, {%0,%1,%2,%3};" \
                 : "+f"((d)[0]), "+f"((d)[1]), "+f"((d)[2]), "+f"((d)[3]) \
                 : "r"((a)[0]), "r"((a)[1]), "r"((a)[2]), "r"((a)[3]),   \
                   "r"(b0), "r"(b1))
#define CP_ASYNC16(dst, src)                                             \
    asm volatile("cp.async.ca.shared.global [%0], [%1], 16;" :: "r"(dst), "l"(src))
#define CP_COMMIT() asm volatile("cp.async.commit_group;")
#define CP_WAIT0()  asm volatile("cp.async.wait_group 0;" ::: "memory")

__device__ __forceinline__ uint32_t pack_h2(__half a, __half b) {
    __half2 p{a, b};
    return *(uint32_t*)&p;
}
__device__ __forceinline__ uint32_t pack_f2h(float a, float b) {
    return pack_h2(__float2half_rn(a), __float2half_rn(b));
}
__device__ __forceinline__ float ex2f(float x) {
    float y;
    asm("ex2.approx.ftz.f32 %0, %1;" : "=f"(y) : "f"(x));
    return y;
}
// pack 4 floats into hi(uint2) / lo(uint2)
__device__ __forceinline__ void split4(float4 v, uint2& hi, uint2& lo) {
    __half a0 = __float2half_rn(v.x), a1 = __float2half_rn(v.y);
    __half a2 = __float2half_rn(v.z), a3 = __float2half_rn(v.w);
    hi = make_uint2(pack_h2(a0, a1), pack_h2(a2, a3));
    lo = make_uint2(pack_f2h(v.x - __half2float(a0), v.y - __half2float(a1)),
                    pack_f2h(v.z - __half2float(a2), v.w - __half2float(a3)));
}

// ---------------- pure-tensor fp16 hi/lo GEMM ------
#define ROWB 80
#define OFF_AHI 0
#define OFF_ALO 10240
#define OFF_B   20480
#define BUFSZ   30720
#define GEMM_SMEM (2 * BUFSZ)

template<bool RELU>
__global__ __launch_bounds__(256, 2)
void mma_gemm(const __half* __restrict__ Ahi, const __half* __restrict__ Alo,
              const int* __restrict__ a_inv, const __half* __restrict__ W,
              const float* __restrict__ bias, const float* __restrict__ res,
              const int* __restrict__ c_inv, float* __restrict__ C32,
              __half* __restrict__ Chi, __half* __restrict__ Clo,
              float* __restrict__ stats, int Nc, int K) {
    extern __shared__ char smem[];
    const uint32_t sb = smem_u32(smem);
    const int tid = threadIdx.x;
    const int wid = tid >> 5, lane = tid & 31;
    const int wm = (wid >> 1) * 32, wn = (wid & 1) * 64;
    const int row0 = blockIdx.y * 128;
    const int col0 = blockIdx.x * 128;
    const int r = tid >> 1, half = tid & 1;

    const __half *pAhi, *pAlo;
    bool avalid = true;
    {
        int arow = row0 + r;
        if (a_inv) {
            int nd = a_inv[arow];
            avalid = nd >= 0;
            int nn = avalid ? nd : 0;
            pAhi = Ahi + (size_t)nn * K;
            pAlo = Alo + (size_t)nn * K;
        } else {
            pAhi = Ahi + (size_t)arow * K;
            pAlo = Alo + (size_t)arow * K;
        }
    }

    float acc[2][8][4];
#pragma unroll
    for (int mt = 0; mt < 2; mt++)
#pragma unroll
        for (int nt = 0; nt < 8; nt++)
#pragma unroll
            for (int q = 0; q < 4; q++) acc[mt][nt][q] = 0.f;

    const int nit = K >> 5;

    auto issue = [&](int i) {
        const uint32_t bo = (uint32_t)(i & 1) * BUFSZ;
        const int k0 = i * 32;
        const char* sAh = avalid ? (const char*)(pAhi + k0 + half * 16)
                                 : (const char*)(g_zrow + half * 16);
        const char* sAl = avalid ? (const char*)(pAlo + k0 + half * 16)
                                 : (const char*)(g_zrow + half * 16);
        uint32_t dA = sb + bo + OFF_AHI + r * ROWB + half * 32;
        CP_ASYNC16(dA, sAh); CP_ASYNC16(dA + 16, sAh + 16);
        uint32_t dL = sb + bo + OFF_ALO + r * ROWB + half * 32;
        CP_ASYNC16(dL, sAl); CP_ASYNC16(dL + 16, sAl + 16);
        const char* gb = (const char*)(W + (size_t)(col0 + r) * K + k0 + half * 16);
        uint32_t dB = sb + bo + OFF_B + r * ROWB + half * 32;
        CP_ASYNC16(dB, gb); CP_ASYNC16(dB + 16, gb + 16);
        CP_COMMIT();
    };

    issue(0);
    for (int i = 0; i < nit; i++) {
        const uint32_t boff = (uint32_t)(i & 1) * BUFSZ;
        CP_WAIT0();
        __syncthreads();
        if (i + 1 < nit) issue(i + 1);
#pragma unroll
        for (int ks = 0; ks < 2; ks++) {
            uint32_t ah[2][4], al[2][4];
#pragma unroll
            for (int mt = 0; mt < 2; mt++) {
                uint32_t arow = wm + mt * 16 + (lane & 15);
                uint32_t kb = ks * 32 + ((lane >> 4) * 16);
                uint32_t ad = sb + boff + OFF_AHI + arow * ROWB + kb;
                LDSM_X4(ah[mt][0], ah[mt][1], ah[mt][2], ah[mt][3], ad);
                LDSM_X4(al[mt][0], al[mt][1], al[mt][2], al[mt][3],
                        ad + (OFF_ALO - OFF_AHI));
            }
#pragma unroll
            for (int np = 0; np < 4; np++) {
                uint32_t nrow = wn + np * 16 + ((lane >> 4) << 3) + (lane & 7);
                uint32_t kb = ks * 32 + (((lane >> 3) & 1) << 4);
                uint32_t bd = sb + boff + OFF_B + nrow * ROWB + kb;
                uint32_t bh[4];
                LDSM_X4(bh[0], bh[1], bh[2], bh[3], bd);
#pragma unroll
                for (int mt = 0; mt < 2; mt++) {
                    MMA16816(acc[mt][2 * np],     ah[mt], bh[0], bh[1]);
                    MMA16816(acc[mt][2 * np],     al[mt], bh[0], bh[1]);
                    MMA16816(acc[mt][2 * np + 1], ah[mt], bh[2], bh[3]);
                    MMA16816(acc[mt][2 * np + 1], al[mt], bh[2], bh[3]);
                }
            }
        }
        // no trailing sync: next-iter top sync orders buffer reuse
    }
    __syncthreads();   // guard smem reuse in epilogue

    // ---- epilogue ----
    float* ssum = (float*)smem;
    float* ssq  = ssum + 128;
    if (stats) {
        if (tid < 128) { ssum[tid] = 0.f; ssq[tid] = 0.f; }
        __syncthreads();
    }
    int rA0 = row0 + wm + (lane >> 2);
    int nmap[2][2];
    if (c_inv) {
        nmap[0][0] = c_inv[rA0];      nmap[0][1] = c_inv[rA0 + 8];
        nmap[1][0] = c_inv[rA0 + 16]; nmap[1][1] = c_inv[rA0 + 24];
    }
#pragma unroll
    for (int nt = 0; nt < 8; nt++) {
        int c = col0 + wn + nt * 8 + (lane & 3) * 2;
        float2 bi = *(const float2*)(bias + c);
        float cs0 = 0.f, cs1 = 0.f, cq0 = 0.f, cq1 = 0.f;
#pragma unroll
        for (int mt = 0; mt < 2; mt++) {
            int ra = rA0 + mt * 16;
            float o0 = acc[mt][nt][0] + bi.x, o1 = acc[mt][nt][1] + bi.y;
            float o2 = acc[mt][nt][2] + bi.x, o3 = acc[mt][nt][3] + bi.y;
            if (c_inv) {
                int na = nmap[mt][0], nb = nmap[mt][1];
                if (na >= 0) {
                    float2 rv = *(const float2*)(res + (size_t)na * Nc + c);
                    o0 += rv.x; o1 += rv.y;
                    *(float2*)(C32 + (size_t)na * Nc + c) = make_float2(o0, o1);
                    cs0 += o0; cq0 += o0 * o0; cs1 += o1; cq1 += o1 * o1;
                }
                if (nb >= 0) {
                    float2 rv = *(const float2*)(res + (size_t)nb * Nc + c);
                    o2 += rv.x; o3 += rv.y;
                    *(float2*)(C32 + (size_t)nb * Nc + c) = make_float2(o2, o3);
                    cs0 += o2; cq0 += o2 * o2; cs1 += o3; cq1 += o3 * o3;
                }
            } else {
                if (res) {
                    float2 r0 = *(const float2*)(res + (size_t)ra * Nc + c);
                    float2 r1 = *(const float2*)(res + (size_t)(ra + 8) * Nc + c);
                    o0 += r0.x; o1 += r0.y; o2 += r1.x; o3 += r1.y;
                }
                if (RELU) {
                    o0 = fmaxf(o0, 0.f); o1 = fmaxf(o1, 0.f);
                    o2 = fmaxf(o2, 0.f); o3 = fmaxf(o3, 0.f);
                }
                if (C32) {
                    *(float2*)(C32 + (size_t)ra * Nc + c) = make_float2(o0, o1);
                    *(float2*)(C32 + (size_t)(ra + 8) * Nc + c) = make_float2(o2, o3);
                }
                if (Chi) {
                    __half h0 = __float2half_rn(o0), h1 = __float2half_rn(o1);
                    __half h2 = __float2half_rn(o2), h3 = __float2half_rn(o3);
                    *(uint32_t*)(Chi + (size_t)ra * Nc + c) = pack_h2(h0, h1);
                    *(uint32_t*)(Clo + (size_t)ra * Nc + c) =
                        pack_f2h(o0 - __half2float(h0), o1 - __half2float(h1));
                    *(uint32_t*)(Chi + (size_t)(ra + 8) * Nc + c) = pack_h2(h2, h3);
                    *(uint32_t*)(Clo + (size_t)(ra + 8) * Nc + c) =
                        pack_f2h(o2 - __half2float(h2), o3 - __half2float(h3));
                }
                if (stats) {
                    cs0 += o0 + o2; cq0 += o0 * o0 + o2 * o2;
                    cs1 += o1 + o3; cq1 += o1 * o1 + o3 * o3;
                }
            }
        }
        if (stats) {
            int lc = c - col0;
            atomicAdd(&ssum[lc], cs0); atomicAdd(&ssq[lc], cq0);
            atomicAdd(&ssum[lc + 1], cs1); atomicAdd(&ssq[lc + 1], cq1);
        }
    }
    if (stats) {
        __syncthreads();
        if (tid < 128) {
            atomicAdd(&stats[col0 + tid], ssum[tid]);
            atomicAdd(&stats[Hc + col0 + tid], ssq[tid]);
        }
    }
}

// ---------------- weight convert + deg zero ---------
__global__ void wsplit_all(const float* w0, const float* w1, const float* w2,
                           const float* w3, const float* w4, const float* w5) {
    int blk = blockIdx.x;
    int gid = blk * 256 + threadIdx.x;
    if (gid < NMAX) g_deg[gid] = 0;
    const float* W; int sblk; int oel;
    if      (blk < 64)  { W = w0; sblk = 0;   oel = 0;      }
    else if (blk < 128) { W = w1; sblk = 64;  oel = 65536;  }
    else if (blk < 320) { W = w2; sblk = 128; oel = 131072; }
    else if (blk < 384) { W = w3; sblk = 320; oel = 327680; }
    else if (blk < 512) { W = w4; sblk = 384; oel = 393216; }
    else                { W = w5; sblk = 512; oel = 524288; }
    int i4 = (blk - sblk) * 256 + threadIdx.x;
    float4 v = ((const float4*)W)[i4];
    ((uint2*)(g_wh + oel))[i4] = make_uint2(pack_f2h(v.x, v.y), pack_f2h(v.z, v.w));
}

// ---------------- CSR build ------------------------
__global__ void hist_k(const int* __restrict__ dst, int E) {
    int e = blockIdx.x * 256 + threadIdx.x;
    if (e < E) atomicAdd(&g_deg[dst[e]], 1);
}

// single block, 1024 threads, 32 items each (nN = 32768 exactly)
__global__ void csr_scan() {
    __shared__ int sm[1024];
    int t = threadIdx.x;
    int base = t * 32;
    int loc[32];
    int s = 0;
#pragma unroll
    for (int i = 0; i < 32; i++) { loc[i] = s; s += g_deg[base + i]; }
    sm[t] = s;
    __syncthreads();
    for (int off = 1; off < 1024; off <<= 1) {
        int v = sm[t] + ((t >= off) ? sm[t - off] : 0);
        __syncthreads();
        sm[t] = v;
        __syncthreads();
    }
    int pref = (t == 0) ? 0 : sm[t - 1];
#pragma unroll
    for (int i = 0; i < 32; i++) {
        int v = pref + loc[i];
        g_cs[base + i] = v;
        g_cur[base + i] = v;
    }
    if (t == 1023) g_cs[NMAX] = sm[1023];
}

__global__ void csr_fill(const int* __restrict__ src, const int* __restrict__ dst, int E) {
    int e = blockIdx.x * 256 + threadIdx.x;
    if (e >= E) return;
    int d = dst[e];
    int pos = atomicAdd(&g_cur[d], 1);
    g_csrc[pos] = src[e];
}

// ---------------- fused gather + convert ------------
// warp per dst node: acc = h[n] + sum_{e in CSR[n]} h[src[e]]
// emits h16hi/lo (= h) and ha16hi/lo (= h+agg)
__global__ __launch_bounds__(256)
void gather_k(const float* __restrict__ h) {
    int w = blockIdx.x * 8 + (threadIdx.x >> 5);
    int lane = threadIdx.x & 31;
    const float4* hr = (const float4*)h + (size_t)w * H4c + lane * 2;
    float4 a0 = hr[0], a1 = hr[1];
    {
        uint2 hi0, lo0, hi1, lo1;
        split4(a0, hi0, lo0); split4(a1, hi1, lo1);
        uint4* dhi = (uint4*)(g_h16hi + (size_t)w * Hc + lane * 8);
        uint4* dlo = (uint4*)(g_h16lo + (size_t)w * Hc + lane * 8);
        *dhi = make_uint4(hi0.x, hi0.y, hi1.x, hi1.y);
        *dlo = make_uint4(lo0.x, lo0.y, lo1.x, lo1.y);
    }
    float4 s0 = a0, s1 = a1;
    int beg = g_cs[w], end = g_cs[w + 1];
    for (int e = beg; e < end; e++) {
        int src = __ldg(&g_csrc[e]);
        const float4* p = (const float4*)h + (size_t)src * H4c + lane * 2;
        float4 v0 = __ldg(p), v1 = __ldg(p + 1);
        s0.x += v0.x; s0.y += v0.y; s0.z += v0.z; s0.w += v0.w;
        s1.x += v1.x; s1.y += v1.y; s1.z += v1.z; s1.w += v1.w;
    }
    uint2 hi0, lo0, hi1, lo1;
    split4(s0, hi0, lo0); split4(s1, hi1, lo1);
    uint4* dhi = (uint4*)(g_ha16hi + (size_t)w * Hc + lane * 8);
    uint4* dlo = (uint4*)(g_ha16lo + (size_t)w * Hc + lane * 8);
    *dhi = make_uint4(hi0.x, hi0.y, hi1.x, hi1.y);
    *dlo = make_uint4(lo0.x, lo0.y, lo1.x, lo1.y);
}

// ---------------- misc utility ----------------------
__global__ void inv_k(const int* __restrict__ bnn) {
    __shared__ int sm[256];
    int t = threadIdx.x;
    sm[t] = bnn[t];
    __syncthreads();
    for (int off = 1; off < 256; off <<= 1) {
        int v = sm[t] + ((t >= off) ? sm[t - off] : 0);
        __syncthreads();
        sm[t] = v;
        __syncthreads();
    }
    int s = blockIdx.x * 256 + t;
    int b = s >> 7, rr = s & (Mc - 1);
    int cumb = (b == 0) ? 0 : sm[b - 1];
    int nb = sm[b] - cumb;
    bool v = rr < nb;
    g_inv[s] = v ? (cumb + rr) : -1;
    g_mask[s] = v ? 1 : 0;
    if (blockIdx.x == 0) {
        for (int i = t; i < 6 * Hc; i += 256) g_bnstats[i] = 0.f;
    }
}

__device__ __forceinline__ float4 bn4(float4 x, float4 s, float4 q,
                                      float4 g, float4 b, float invN) {
    float4 o;
    { float m = s.x * invN, v = q.x * invN - m * m; o.x = g.x * (x.x - m) * rsqrtf(v + 1e-5f) + b.x; }
    { float m = s.y * invN, v = q.y * invN - m * m; o.y = g.y * (x.y - m) * rsqrtf(v + 1e-5f) + b.y; }
    { float m = s.z * invN, v = q.z * invN - m * m; o.z = g.z * (x.z - m) * rsqrtf(v + 1e-5f) + b.z; }
    { float m = s.w * invN, v = q.w * invN - m * m; o.w = g.w * (x.w - m) * rsqrtf(v + 1e-5f) + b.w; }
    return o;
}

__global__ void bn_combine(const float* __restrict__ PL, const float* __restrict__ PA,
                           const float* __restrict__ gl, const float* __restrict__ bl,
                           const float* __restrict__ ga, const float* __restrict__ ba,
                           const float* __restrict__ stl, const float* __restrict__ sta,
                           float* __restrict__ out, float invN, int n4tot) {
    int gid = blockIdx.x * 256 + threadIdx.x;
    if (gid >= n4tot) return;
    int c4 = gid & 63;
    float4 a = bn4(((const float4*)PL)[gid], ((const float4*)stl)[c4],
                   ((const float4*)stl)[H4c + c4], ((const float4*)gl)[c4],
                   ((const float4*)bl)[c4], invN);
    float4 b = bn4(((const float4*)PA)[gid], ((const float4*)sta)[c4],
                   ((const float4*)sta)[H4c + c4], ((const float4*)ga)[c4],
                   ((const float4*)ba)[c4], invN);
    a.x += b.x; a.y += b.y; a.z += b.z; a.w += b.w;
    ((float4*)out)[gid] = a;
    __half h0 = __float2half_rn(a.x), h1 = __float2half_rn(a.y);
    __half h2 = __float2half_rn(a.z), h3 = __float2half_rn(a.w);
    ((uint2*)g_hh16hi)[gid] = make_uint2(pack_h2(h0, h1), pack_h2(h2, h3));
    ((uint2*)g_hh16lo)[gid] = make_uint2(
        pack_f2h(a.x - __half2float(h0), a.y - __half2float(h1)),
        pack_f2h(a.z - __half2float(h2), a.w - __half2float(h3)));
}

__global__ void bn_apply(const float* __restrict__ X, const float* __restrict__ st,
                         const float* __restrict__ gamma, const float* __restrict__ beta,
                         float* __restrict__ out, float invN, int n4total) {
    int gid = blockIdx.x * 256 + threadIdx.x;
    if (gid >= n4total) return;
    int c4 = gid & 63;
    float4 o = bn4(((const float4*)X)[gid], ((const float4*)st)[c4],
                   ((const float4*)st)[H4c + c4], ((const float4*)gamma)[c4],
                   ((const float4*)beta)[c4], invN);
    ((float4*)out)[gid] = o;
}

// ---------------- tensor-core attention -------------
#define AQHI 0
#define AQLO 10240
#define AKS  20480
#define AVT  30720
#define AMB  39424
#define ASMEM 39936

__global__ __launch_bounds__(128)
void attn_mma() {
    __shared__ char smem[ASMEM];
    const uint32_t sb = smem_u32(smem);
    const int b = blockIdx.x >> 3;
    const int head = blockIdx.x & 7;
    const int tid = threadIdx.x;
    const int wid = tid >> 5, lane = tid & 31;
    const int wm = wid * 32;

    const float sc2 = 0.17677669529663687f * 1.44269504088896341f;

    {
        const float* base = g_qkv + (size_t)(b * Mc + tid) * (3 * Hc);
        const float* qp = base + head * DHc;
        const float* kp = base + Hc + head * DHc;
        const float* vp = base + 2 * Hc + head * DHc;
#pragma unroll
        for (int j = 0; j < 8; j++) {
            float4 q4 = *(const float4*)(qp + j * 4);
            q4.x *= sc2; q4.y *= sc2; q4.z *= sc2; q4.w *= sc2;
            __half hx = __float2half_rn(q4.x), hy = __float2half_rn(q4.y);
            __half hz = __float2half_rn(q4.z), hw = __float2half_rn(q4.w);
            *(uint2*)(smem + AQHI + tid * ROWB + j * 8) =
                make_uint2(pack_h2(hx, hy), pack_h2(hz, hw));
            *(uint2*)(smem + AQLO + tid * ROWB + j * 8) = make_uint2(
                pack_f2h(q4.x - __half2float(hx), q4.y - __half2float(hy)),
                pack_f2h(q4.z - __half2float(hz), q4.w - __half2float(hw)));
            float4 k4 = *(const float4*)(kp + j * 4);
            *(uint2*)(smem + AKS + tid * ROWB + j * 8) =
                make_uint2(pack_f2h(k4.x, k4.y), pack_f2h(k4.z, k4.w));
            float4 v4 = *(const float4*)(vp + j * 4);
            __half* vt = (__half*)(smem + AVT);
            vt[(j * 4 + 0) * 136 + tid] = __float2half_rn(v4.x);
            vt[(j * 4 + 1) * 136 + tid] = __float2half_rn(v4.y);
            vt[(j * 4 + 2) * 136 + tid] = __float2half_rn(v4.z);
            vt[(j * 4 + 3) * 136 + tid] = __float2half_rn(v4.w);
        }
        ((float*)(smem + AMB))[tid] = g_mask[b * Mc + tid] ? 0.f : -1e30f;
    }
    __syncthreads();

    float sc[2][16][4];
#pragma unroll
    for (int mt = 0; mt < 2; mt++)
#pragma unroll
        for (int nt = 0; nt < 16; nt++)
#pragma unroll
            for (int q = 0; q < 4; q++) sc[mt][nt][q] = 0.f;

#pragma unroll
    for (int pass = 0; pass < 2; pass++) {
        const uint32_t aoff = pass ? AQLO : AQHI;
#pragma unroll
        for (int ks = 0; ks < 2; ks++) {
            uint32_t ah[2][4];
#pragma unroll
            for (int mt = 0; mt < 2; mt++) {
                uint32_t arow = wm + mt * 16 + (lane & 15);
                uint32_t kb = ks * 32 + ((lane >> 4) * 16);
                LDSM_X4(ah[mt][0], ah[mt][1], ah[mt][2], ah[mt][3],
                        sb + aoff + arow * ROWB + kb);
            }
#pragma unroll
            for (int np = 0; np < 8; np++) {
                uint32_t nrow = np * 16 + ((lane >> 4) << 3) + (lane & 7);
                uint32_t kb = ks * 32 + (((lane >> 3) & 1) << 4);
                uint32_t bh[4];
                LDSM_X4(bh[0], bh[1], bh[2], bh[3], sb + AKS + nrow * ROWB + kb);
#pragma unroll
                for (int mt = 0; mt < 2; mt++) {
                    MMA16816(sc[mt][2 * np],     ah[mt], bh[0], bh[1]);
                    MMA16816(sc[mt][2 * np + 1], ah[mt], bh[2], bh[3]);
                }
            }
        }
    }

    const float* mb = (const float*)(smem + AMB);
#pragma unroll
    for (int nt = 0; nt < 16; nt++) {
        float2 mp = *(const float2*)(mb + nt * 8 + (lane & 3) * 2);
#pragma unroll
        for (int mt = 0; mt < 2; mt++) {
            sc[mt][nt][0] += mp.x; sc[mt][nt][1] += mp.y;
            sc[mt][nt][2] += mp.x; sc[mt][nt][3] += mp.y;
        }
    }
    float rinv[4];
#pragma unroll
    for (int rg = 0; rg < 4; rg++) {
        const int mt = rg >> 1, off = (rg & 1) * 2;
        float m = -3.0e38f;
#pragma unroll
        for (int nt = 0; nt < 16; nt++)
            m = fmaxf(m, fmaxf(sc[mt][nt][off], sc[mt][nt][off + 1]));
        m = fmaxf(m, __shfl_xor_sync(0xffffffff, m, 1));
        m = fmaxf(m, __shfl_xor_sync(0xffffffff, m, 2));
        float l = 0.f;
#pragma unroll
        for (int nt = 0; nt < 16; nt++) {
            float p0 = ex2f(sc[mt][nt][off] - m);
            float p1 = ex2f(sc[mt][nt][off + 1] - m);
            sc[mt][nt][off] = p0; sc[mt][nt][off + 1] = p1;
            l += p0 + p1;
        }
        l += __shfl_xor_sync(0xffffffff, l, 1);
        l += __shfl_xor_sync(0xffffffff, l, 2);
        rinv[rg] = 1.f / l;
    }

    float av[2][4][4];
#pragma unroll
    for (int mt = 0; mt < 2; mt++)
#pragma unroll
        for (int nd = 0; nd < 4; nd++)
#pragma unroll
            for (int q = 0; q < 4; q++) av[mt][nd][q] = 0.f;

#pragma unroll
    for (int j = 0; j < 8; j++) {
        uint32_t pa[2][4];
#pragma unroll
        for (int mt = 0; mt < 2; mt++) {
            pa[mt][0] = pack_f2h(sc[mt][2 * j][0],     sc[mt][2 * j][1]);
            pa[mt][1] = pack_f2h(sc[mt][2 * j][2],     sc[mt][2 * j][3]);
            pa[mt][2] = pack_f2h(sc[mt][2 * j + 1][0], sc[mt][2 * j + 1][1]);
            pa[mt][3] = pack_f2h(sc[mt][2 * j + 1][2], sc[mt][2 * j + 1][3]);
        }
#pragma unroll
        for (int np = 0; np < 2; np++) {
            uint32_t nrow = np * 16 + ((lane >> 4) << 3) + (lane & 7);
            uint32_t kb = j * 32 + (((lane >> 3) & 1) << 4);
            uint32_t vb[4];
            LDSM_X4(vb[0], vb[1], vb[2], vb[3], sb + AVT + nrow * 272 + kb);
#pragma unroll
            for (int mt = 0; mt < 2; mt++) {
                MMA16816(av[mt][2 * np],     pa[mt], vb[0], vb[1]);
                MMA16816(av[mt][2 * np + 1], pa[mt], vb[2], vb[3]);
            }
        }
    }

#pragma unroll
    for (int mt = 0; mt < 2; mt++) {
        int row = b * Mc + wm + mt * 16 + (lane >> 2);
#pragma unroll
        for (int nd = 0; nd < 4; nd++) {
            int col = head * DHc + nd * 8 + (lane & 3) * 2;
            float i0 = rinv[mt * 2 + 0], i1 = rinv[mt * 2 + 1];
            float x0 = av[mt][nd][0] * i0, x1 = av[mt][nd][1] * i0;
            float x2 = av[mt][nd][2] * i1, x3 = av[mt][nd][3] * i1;
            __half h0 = __float2half_rn(x0), h1 = __float2half_rn(x1);
            __half h2 = __float2half_rn(x2), h3 = __float2half_rn(x3);
            *(uint32_t*)(g_ad16hi + (size_t)row * Hc + col) = pack_h2(h0, h1);
            *(uint32_t*)(g_ad16lo + (size_t)row * Hc + col) =
                pack_f2h(x0 - __half2float(h0), x1 - __half2float(h1));
            *(uint32_t*)(g_ad16hi + (size_t)(row + 8) * Hc + col) = pack_h2(h2, h3);
            *(uint32_t*)(g_ad16lo + (size_t)(row + 8) * Hc + col) =
                pack_f2h(x2 - __half2float(h2), x3 - __half2float(h3));
        }
    }
}

// ---------------- host orchestration ----------------
static inline int cdiv(long a, int b) { return (int)((a + b - 1) / b); }

extern "C" void kernel_launch(void* const* d_in, const int* in_sizes, int n_in,
                              void* d_out, int out_size) {
    const float* h         = (const float*)d_in[0];
    const float* gin_w1    = (const float*)d_in[1];
    const float* gin_b1    = (const float*)d_in[2];
    const float* gin_w2    = (const float*)d_in[3];
    const float* gin_b2    = (const float*)d_in[4];
    const float* in_proj_w = (const float*)d_in[5];
    const float* in_proj_b = (const float*)d_in[6];
    const float* out_proj_w= (const float*)d_in[7];
    const float* out_proj_b= (const float*)d_in[8];
    const float* bnl_g     = (const float*)d_in[9];
    const float* bnl_b     = (const float*)d_in[10];
    const float* bna_g     = (const float*)d_in[11];
    const float* bna_b     = (const float*)d_in[12];
    const float* bno_g     = (const float*)d_in[13];
    const float* bno_b     = (const float*)d_in[14];
    const float* ffn1_w    = (const float*)d_in[15];
    const float* ffn1_b    = (const float*)d_in[16];
    const float* ffn2_w    = (const float*)d_in[17];
    const float* ffn2_b    = (const float*)d_in[18];
    const int*   e_src     = (const int*)d_in[19];
    const int*   e_dst     = (const int*)d_in[20];
    const int*   bnn       = (const int*)d_in[21];

    const int nN = in_sizes[0] / Hc;
    const int nE = in_sizes[19];
    const int n4 = nN * H4c;
    const float invN = 1.0f / (float)nN;

    float *p_PL, *p_PA, *p_PO, *p_qkv, *p_hh, *p_st;
    int *p_inv;
    __half *p_wh, *p_hhi, *p_hlo, *p_hahi, *p_halo, *p_z1hi, *p_z1lo,
           *p_adhi, *p_adlo, *p_hhhi, *p_hhlo, *p_f1hi, *p_f1lo;
    cudaGetSymbolAddress((void**)&p_PL,   g_PL);
    cudaGetSymbolAddress((void**)&p_PA,   g_PA);
    cudaGetSymbolAddress((void**)&p_PO,   g_PO);
    cudaGetSymbolAddress((void**)&p_qkv,  g_qkv);
    cudaGetSymbolAddress((void**)&p_hh,   g_hh);
    cudaGetSymbolAddress((void**)&p_st,   g_bnstats);
    cudaGetSymbolAddress((void**)&p_inv,  g_inv);
    cudaGetSymbolAddress((void**)&p_wh,   g_wh);
    cudaGetSymbolAddress((void**)&p_hhi,  g_h16hi);
    cudaGetSymbolAddress((void**)&p_hlo,  g_h16lo);
    cudaGetSymbolAddress((void**)&p_hahi, g_ha16hi);
    cudaGetSymbolAddress((void**)&p_halo, g_ha16lo);
    cudaGetSymbolAddress((void**)&p_z1hi, g_z116hi);
    cudaGetSymbolAddress((void**)&p_z1lo, g_z116lo);
    cudaGetSymbolAddress((void**)&p_adhi, g_ad16hi);
    cudaGetSymbolAddress((void**)&p_adlo, g_ad16lo);
    cudaGetSymbolAddress((void**)&p_hhhi, g_hh16hi);
    cudaGetSymbolAddress((void**)&p_hhlo, g_hh16lo);
    cudaGetSymbolAddress((void**)&p_f1hi, g_f116hi);
    cudaGetSymbolAddress((void**)&p_f1lo, g_f116lo);

    float* st_l = p_st;
    float* st_a = p_st + 2 * Hc;
    float* st_o = p_st + 4 * Hc;

    cudaFuncSetAttribute(mma_gemm<true>,  cudaFuncAttributeMaxDynamicSharedMemorySize, GEMM_SMEM);
    cudaFuncSetAttribute(mma_gemm<false>, cudaFuncAttributeMaxDynamicSharedMemorySize, GEMM_SMEM);

    const int OFF_GIN1 = 0;
    const int OFF_GIN2 = 65536;
    const int OFF_QKV  = 131072;
    const int OFF_OUT  = 327680;
    const int OFF_F1   = 393216;
    const int OFF_F2   = 524288;

    auto gemm = [&](bool relu, const __half* Ahi, const __half* Alo,
                    const int* a_inv, int woff, const float* bias,
                    const float* res, const int* c_inv, float* C32,
                    __half* Chi, __half* Clo, float* stats, int Nc, int K) {
        dim3 grid(Nc / 128, nN / 128);
        if (relu)
            mma_gemm<true><<<grid, 256, GEMM_SMEM>>>(Ahi, Alo, a_inv, p_wh + woff,
                bias, res, c_inv, C32, Chi, Clo, stats, Nc, K);
        else
            mma_gemm<false><<<grid, 256, GEMM_SMEM>>>(Ahi, Alo, a_inv, p_wh + woff,
                bias, res, c_inv, C32, Chi, Clo, stats, Nc, K);
    };

    // prep: weights + deg zero | CSR build | index | fused gather+convert
    wsplit_all<<<640, 256>>>(gin_w1, gin_w2, in_proj_w, out_proj_w, ffn1_w, ffn2_w);
    hist_k<<<cdiv(nE, 256), 256>>>(e_dst, nE);
    csr_scan<<<1, 1024>>>();
    csr_fill<<<cdiv(nE, 256), 256>>>(e_src, e_dst, nE);
    inv_k<<<Bc * Mc / 256, 256>>>(bnn);
    gather_k<<<nN / 8, 256>>>(h);

    // GIN branch
    gemm(true,  p_hahi, p_halo, nullptr, OFF_GIN1, gin_b1, nullptr, nullptr,
         nullptr, p_z1hi, p_z1lo, nullptr, Hc, Hc);
    gemm(false, p_z1hi, p_z1lo, nullptr, OFF_GIN2, gin_b2, h, nullptr,
         p_PL, nullptr, nullptr, st_l, Hc, Hc);

    // attention branch
    gemm(false, p_hhi, p_hlo, p_inv, OFF_QKV, in_proj_b, nullptr, nullptr,
         p_qkv, nullptr, nullptr, nullptr, 3 * Hc, Hc);
    attn_mma<<<Bc * NHc, 128>>>();
    gemm(false, p_adhi, p_adlo, nullptr, OFF_OUT, out_proj_b, h, p_inv,
         p_PA, nullptr, nullptr, st_a, Hc, Hc);

    // combine BNs
    bn_combine<<<cdiv(n4, 256), 256>>>(p_PL, p_PA, bnl_g, bnl_b, bna_g, bna_b,
                                       st_l, st_a, p_hh, invN, n4);

    // FFN + final norm
    gemm(true,  p_hhhi, p_hhlo, nullptr, OFF_F1, ffn1_b, nullptr, nullptr,
         nullptr, p_f1hi, p_f1lo, nullptr, 2 * Hc, Hc);
    gemm(false, p_f1hi, p_f1lo, nullptr, OFF_F2, ffn2_b, p_hh, nullptr,
         p_PO, nullptr, nullptr, st_o, Hc, 2 * Hc);
    bn_apply<<<cdiv(n4, 256), 256>>>(p_PO, st_o, bno_g, bno_b, (float*)d_out, invN, n4);
}